// round 16
// baseline (speedup 1.0000x reference)
#include <cuda_runtime.h>
#include <cuda_bf16.h>
#include <math.h>

// ---------------------------------------------------------------------------
// ComplexRecurrentModel on GB300 (sm_103 non-'a' PTX target).
// ROUND 16: T = zf*G recognized as the COMPLEX product T = z*H
// (H = Wq^T conj(Wk)); computed with the Karatsuba-3M kernel (25% fewer
// MMAs than the G form). V re-tiled to 64x32-complex blocks so the mixed
// TV launch packs to ~work/148 instead of rounding up a wave.
// Setup: H^T comp planes (r, i, r+i) via 3 real GEMMs from repacked Wq/Wk.
// ---------------------------------------------------------------------------

#define Bc 4
#define Sc 128
#define Dc 512
#define Mc 4
#define Kc 32
#define NSTEPS 16
#define EPSF 1e-6f
#define SCALEF 0.044194173824159216f   // 512^-0.5

constexpr int ROWS = Bc * Sc;              // 512
constexpr int E2 = 2 * Dc;                 // 1024
constexpr int NBS = Bc * Sc;               // 512
constexpr int NMBS = Mc * NBS;             // 2048
constexpr int DD = Dc * Dc;                // 262144
constexpr int WPLANES = 48;
constexpr size_t MM = (size_t)1 << 20;

// ---- device buffers -------------------------------------------------------
// WP planes: 0..11 Wl comps, 12..23 H^T comps (r,i,s per m), 36..47 Wv comps
__device__ __align__(256) __nv_bfloat16 g_WPH[(size_t)WPLANES * DD];
__device__ __align__(256) __nv_bfloat16 g_WPL[(size_t)WPLANES * DD];
__device__ __align__(256) __nv_bfloat16 g_ABh[8 * MM], g_ABl[8 * MM];  // Ak + 3 Aq planes
__device__ __align__(256) __nv_bfloat16 g_Ch[3 * DD], g_Cl[3 * DD];
__device__ __align__(256) float         g_Z [Mc * ROWS * E2];
__device__ __align__(256) __nv_bfloat16 g_Zh[12 * DD], g_Zl[12 * DD];
__device__ __align__(256) __nv_bfloat16 g_Th[Mc * ROWS * E2], g_Tl[Mc * ROWS * E2];
__device__ __align__(256) __nv_bfloat16 g_Vth[16 * E2 * Sc], g_Vtl[16 * E2 * Sc];
__device__ __align__(256) float         g_logits[16 * Sc * Sc];
__device__ __align__(256) float         g_P [Mc * ROWS * E2];
__device__ __align__(256) float g_sr[ROWS * Dc], g_si[ROWS * Dc];
__device__ __align__(256) float g_acc[ROWS * E2];
__device__ __align__(256) float g_mem[Bc * Kc * E2];
__device__ __align__(256) float g_ptrst[Bc * Kc];
__device__ __align__(256) float g_score[NMBS], g_conf[NMBS], g_halt[NMBS];
__device__ __align__(256) float g_flat[Bc * E2], g_read[Bc * E2];
__device__ __align__(256) float g_gate[Mc * Dc];
__device__ __align__(256) float g_rem[16], g_stsc[16], g_stcf[16], g_coef[16];

// ---------------------------------------------------------------------------
// helpers
// ---------------------------------------------------------------------------
__device__ __forceinline__ unsigned smem_u32(const void* p) {
    unsigned a;
    asm("{ .reg .u64 t; cvta.to.shared.u64 t, %1; cvt.u32.u64 %0, t; }" : "=r"(a) : "l"(p));
    return a;
}
__device__ __forceinline__ void cpasync16(unsigned dst, const void* src) {
    asm volatile("cp.async.cg.shared.global [%0], [%1], 16;" :: "r"(dst), "l"(src) : "memory");
}
__device__ __forceinline__ void cp_commit() {
    asm volatile("cp.async.commit_group;" ::: "memory");
}
template <int N> __device__ __forceinline__ void cp_wait() {
    asm volatile("cp.async.wait_group %0;" :: "n"(N) : "memory");
}
__device__ __forceinline__ void ldmat_x4(unsigned (&r)[4], unsigned addr) {
    asm volatile("ldmatrix.sync.aligned.m8n8.x4.shared.b16 {%0,%1,%2,%3}, [%4];"
                 : "=r"(r[0]), "=r"(r[1]), "=r"(r[2]), "=r"(r[3]) : "r"(addr));
}
__device__ __forceinline__ void mma16816(float (&c)[4], const unsigned* a, const unsigned* b) {
    asm volatile("mma.sync.aligned.m16n8k16.row.col.f32.bf16.bf16.f32 "
                 "{%0,%1,%2,%3}, {%4,%5,%6,%7}, {%8,%9}, {%0,%1,%2,%3};"
                 : "+f"(c[0]), "+f"(c[1]), "+f"(c[2]), "+f"(c[3])
                 : "r"(a[0]), "r"(a[1]), "r"(a[2]), "r"(a[3]), "r"(b[0]), "r"(b[1]));
}
__device__ __forceinline__ unsigned swz128(unsigned off) { return off ^ ((off >> 3) & 0x70); }
__device__ __forceinline__ unsigned pkbf2(float a, float b) {
    __nv_bfloat162 t = __floats2bfloat162_rn(a, b);
    return *(unsigned*)&t;
}
__device__ __forceinline__ float bflo(float v) {
    __nv_bfloat16 h = __float2bfloat16(v);
    return v - __bfloat162float(h);
}
__device__ __forceinline__ float sigm(float x) { return 1.f / (1.f + expf(-x)); }

constexpr int STAGE3M = 98304;              // 96KB (64x64 3M)
constexpr int GEMM3M_SMEM = 2 * STAGE3M;    // 192KB
constexpr int STAGEVS = 73728;              // 72KB (64x32 3M)
constexpr int GEMM_SMEM = 3 * 65536;        // 192KB

struct MmaCtx {
    int warpM, warpN;
    int a_m, a_k, b_n, b_k;
};
__device__ __forceinline__ MmaCtx make_ctx(int tid) {
    MmaCtx cx;
    int wid = tid >> 5, lane = tid & 31;
    cx.warpM = (wid & 3) * 32; cx.warpN = (wid >> 2) * 64;
    int lmat = lane >> 3, lrow = lane & 7;
    cx.a_m = (lmat & 1) * 8 + lrow; cx.a_k = (lmat >> 1) * 8;
    cx.b_n = (lmat >> 1) * 8 + lrow; cx.b_k = (lmat & 1) * 8;
    return cx;
}
__device__ __forceinline__ void mma_compute(const MmaCtx& cx, unsigned stg, float acc[2][8][4]) {
    const unsigned sA0 = stg, sA1 = stg + 16384u;
    const unsigned sB0 = stg + 32768u, sB1 = stg + 49152u;
#pragma unroll
    for (int ks = 0; ks < 4; ks++) {
        unsigned ah[2][4], al[2][4];
#pragma unroll
        for (int mt = 0; mt < 2; mt++) {
            int mm = cx.warpM + mt * 16 + cx.a_m;
            unsigned off = swz128((unsigned)(mm * 128 + (ks * 16 + cx.a_k) * 2));
            ldmat_x4(ah[mt], sA0 + off);
            ldmat_x4(al[mt], sA1 + off);
        }
        unsigned bh[8][2], bl[8][2];
#pragma unroll
        for (int np = 0; np < 4; np++) {
            int n = cx.warpN + np * 16 + cx.b_n;
            unsigned off = swz128((unsigned)(n * 128 + (ks * 16 + cx.b_k) * 2));
            unsigned rh[4], rl[4];
            ldmat_x4(rh, sB0 + off);
            ldmat_x4(rl, sB1 + off);
            bh[2*np][0]=rh[0]; bh[2*np][1]=rh[1]; bh[2*np+1][0]=rh[2]; bh[2*np+1][1]=rh[3];
            bl[2*np][0]=rl[0]; bl[2*np][1]=rl[1]; bl[2*np+1][0]=rl[2]; bl[2*np+1][1]=rl[3];
        }
#pragma unroll
        for (int mt = 0; mt < 2; mt++)
#pragma unroll
            for (int nt = 0; nt < 8; nt++) {
                mma16816(acc[mt][nt], ah[mt], bh[nt]);
                mma16816(acc[mt][nt], ah[mt], bl[nt]);
                mma16816(acc[mt][nt], al[mt], bh[nt]);
            }
    }
}
__device__ __forceinline__ void mma_stage_load(
    int tid, unsigned stg, int k0,
    const __nv_bfloat16* aPh, const __nv_bfloat16* aPl, int aK,
    const __nv_bfloat16* bPh, const __nv_bfloat16* bPl, int bK) {
    const __nv_bfloat16* aa[2] = { aPh, aPl };
    const __nv_bfloat16* bb[2] = { bPh, bPl };
#pragma unroll
    for (int hl = 0; hl < 2; hl++) {
        unsigned hOff = hl ? 16384u : 0u;
#pragma unroll
        for (int it = 0; it < 4; it++) {
            int idx = it * 256 + tid;
            int r = idx >> 3, c = (idx & 7) * 8;
            unsigned so = swz128((unsigned)(r * 128 + c * 2));
            cpasync16(stg + hOff + so, aa[hl] + (size_t)r * aK + k0 + c);
            cpasync16(stg + 32768u + hOff + so, bb[hl] + (size_t)r * bK + k0 + c);
        }
    }
    cp_commit();
}
__device__ __forceinline__ void stage_load_B(
    int tid, unsigned stg, int k0,
    const __nv_bfloat16* bPh, const __nv_bfloat16* bPl, int bK) {
    const __nv_bfloat16* bb[2] = { bPh, bPl };
#pragma unroll
    for (int hl = 0; hl < 2; hl++) {
        unsigned hOff = hl ? 16384u : 0u;
#pragma unroll
        for (int it = 0; it < 4; it++) {
            int idx = it * 256 + tid;
            int r = idx >> 3, c = (idx & 7) * 8;
            unsigned so = swz128((unsigned)(r * 128 + c * 2));
            cpasync16(stg + 32768u + hOff + so, bb[hl] + (size_t)r * bK + k0 + c);
        }
    }
    cp_commit();
}

// ---------------------------------------------------------------------------
// reductions
// ---------------------------------------------------------------------------
__device__ __forceinline__ float blockSum128(float v) {
    __shared__ float sh[4];
    int lane = threadIdx.x & 31, w = threadIdx.x >> 5;
#pragma unroll
    for (int o = 16; o; o >>= 1) v += __shfl_xor_sync(0xffffffffu, v, o);
    if (lane == 0) sh[w] = v;
    __syncthreads();
    float r = sh[0] + sh[1] + sh[2] + sh[3];
    __syncthreads();
    return r;
}
__device__ __forceinline__ float blockSum256(float v, float* sh) {
    int lane = threadIdx.x & 31, w = threadIdx.x >> 5;
#pragma unroll
    for (int o = 16; o; o >>= 1) v += __shfl_xor_sync(0xffffffffu, v, o);
    if (lane == 0) sh[w] = v;
    __syncthreads();
    float r = 0.f;
#pragma unroll
    for (int i = 0; i < 8; i++) r += sh[i];
    __syncthreads();
    return r;
}

// ---------------------------------------------------------------------------
// Wl fused 3M GEMM. grid (8, 8, Mc).
// ---------------------------------------------------------------------------
__global__ void __launch_bounds__(256, 1) gemm_3m_wl(
    const __nv_bfloat16* __restrict__ Ah, const __nv_bfloat16* __restrict__ Al,
    const __nv_bfloat16* __restrict__ Wh, const __nv_bfloat16* __restrict__ Wl,
    float* __restrict__ outZ)
{
    extern __shared__ char smem_raw[];
    const unsigned sbase = smem_u32(smem_raw);
    const int tid = threadIdx.x;
    const int wid = tid >> 5, lane = tid & 31;
    const int m = blockIdx.z;
    const int col0 = blockIdx.x * 64;
    const int row0 = blockIdx.y * 64;

    const int warpM = (wid & 1) * 32, warpN = (wid >> 1) * 16;
    const int lmat = lane >> 3, lrow = lane & 7;
    const int a_m = (lmat & 1) * 8 + lrow, a_k = (lmat >> 1) * 8;
    const int b_n = (lmat >> 1) * 8 + lrow, b_k = (lmat & 1) * 8;

    const size_t bBase = (size_t)m * 3 * DD;
    const __nv_bfloat16* aP[3][2];
    const __nv_bfloat16* bP[3][2];
#pragma unroll
    for (int c = 0; c < 3; c++) {
        aP[c][0] = Ah + (size_t)c * DD + (size_t)row0 * Dc;
        aP[c][1] = Al + (size_t)c * DD + (size_t)row0 * Dc;
        bP[c][0] = Wh + bBase + (size_t)c * DD + (size_t)col0 * Dc;
        bP[c][1] = Wl + bBase + (size_t)c * DD + (size_t)col0 * Dc;
    }

    float acc[3][2][2][4];
#pragma unroll
    for (int p = 0; p < 3; p++)
#pragma unroll
        for (int mt = 0; mt < 2; mt++)
#pragma unroll
            for (int nt = 0; nt < 2; nt++)
#pragma unroll
                for (int q = 0; q < 4; q++) acc[p][mt][nt][q] = 0.f;

    auto stage_load = [&](int ch, unsigned stg) {
        const int k0 = ch << 6;
#pragma unroll
        for (int c = 0; c < 3; c++)
#pragma unroll
            for (int hl = 0; hl < 2; hl++) {
                unsigned tOff = (unsigned)((c * 2 + hl) * 8192);
#pragma unroll
                for (int it = 0; it < 2; it++) {
                    int idx = it * 256 + tid;
                    int r = idx >> 3, cc = (idx & 7) * 8;
                    unsigned so = swz128((unsigned)(r * 128 + cc * 2));
                    cpasync16(stg + tOff + so, aP[c][hl] + (size_t)r * Dc + k0 + cc);
                    cpasync16(stg + 49152u + tOff + so, bP[c][hl] + (size_t)r * Dc + k0 + cc);
                }
            }
        cp_commit();
    };
    auto compute = [&](unsigned stg) {
#pragma unroll
        for (int ks = 0; ks < 4; ks++) {
            unsigned afh[3][2][4], afl[3][2][4];
#pragma unroll
            for (int c = 0; c < 3; c++)
#pragma unroll
                for (int mt = 0; mt < 2; mt++) {
                    int mm = warpM + mt * 16 + a_m;
                    unsigned off = swz128((unsigned)(mm * 128 + (ks * 16 + a_k) * 2));
                    ldmat_x4(afh[c][mt], stg + (unsigned)((c * 2 + 0) * 8192) + off);
                    ldmat_x4(afl[c][mt], stg + (unsigned)((c * 2 + 1) * 8192) + off);
                }
            unsigned bfh[3][2][2], bfl[3][2][2];
#pragma unroll
            for (int c = 0; c < 3; c++) {
                int n = warpN + b_n;
                unsigned off = swz128((unsigned)(n * 128 + (ks * 16 + b_k) * 2));
                unsigned rh[4], rl[4];
                ldmat_x4(rh, stg + 49152u + (unsigned)((c * 2 + 0) * 8192) + off);
                ldmat_x4(rl, stg + 49152u + (unsigned)((c * 2 + 1) * 8192) + off);
                bfh[c][0][0] = rh[0]; bfh[c][0][1] = rh[1];
                bfh[c][1][0] = rh[2]; bfh[c][1][1] = rh[3];
                bfl[c][0][0] = rl[0]; bfl[c][0][1] = rl[1];
                bfl[c][1][0] = rl[2]; bfl[c][1][1] = rl[3];
            }
#pragma unroll
            for (int p = 0; p < 3; p++)
#pragma unroll
                for (int mt = 0; mt < 2; mt++)
#pragma unroll
                    for (int nt = 0; nt < 2; nt++) {
                        mma16816(acc[p][mt][nt], afh[p][mt], bfh[p][nt]);
                        mma16816(acc[p][mt][nt], afh[p][mt], bfl[p][nt]);
                        mma16816(acc[p][mt][nt], afl[p][mt], bfh[p][nt]);
                    }
        }
    };

    const unsigned stg0 = sbase, stg1 = sbase + (unsigned)STAGE3M;
    const int nchunk = 8;
    stage_load(0, stg0);
    for (int ch = 0; ch < nchunk; ch++) {
        unsigned cur = (ch & 1) ? stg1 : stg0;
        if (ch + 1 < nchunk) { stage_load(ch + 1, (ch & 1) ? stg0 : stg1); cp_wait<1>(); }
        else cp_wait<0>();
        __syncthreads();
        compute(cur);
        __syncthreads();
    }

    const int erow = lane >> 2, ecol = (lane & 3) * 2;
#pragma unroll
    for (int mt = 0; mt < 2; mt++)
#pragma unroll
        for (int nt = 0; nt < 2; nt++)
#pragma unroll
            for (int half = 0; half < 2; half++) {
                int rowG = row0 + warpM + mt * 16 + erow + half * 8;
                int colG = col0 + warpN + nt * 8 + ecol;
                float m1a = acc[0][mt][nt][half * 2],     m1b = acc[0][mt][nt][half * 2 + 1];
                float m2a = acc[1][mt][nt][half * 2],     m2b = acc[1][mt][nt][half * 2 + 1];
                float m3a = acc[2][mt][nt][half * 2],     m3b = acc[2][mt][nt][half * 2 + 1];
                float* o = outZ + ((size_t)m * ROWS + rowG) * E2 + colG;
                o[0] = m1a - m2a; o[1] = m1b - m2b;
                o[Dc] = m3a - m1a - m2a; o[Dc + 1] = m3b - m1b - m2b;
            }
}

// ---------------------------------------------------------------------------
// FUSED T + V kernel. grid (768):
//   bid < 256 -> T = z*H (3M 64x64 complex, K=512, packed row-major out)
//   else      -> V = z*Wv (3M 64x32 complex, K=512, transposed out)
// WH/WL planes: H^T at 12 + m*3 + c ; Wv at 36 + m*3 + c.
// ---------------------------------------------------------------------------
__global__ void __launch_bounds__(256, 1) gemm_TV(
    const __nv_bfloat16* __restrict__ Zh_, const __nv_bfloat16* __restrict__ Zl_,
    const __nv_bfloat16* __restrict__ WH, const __nv_bfloat16* __restrict__ WL,
    __nv_bfloat16* __restrict__ Th_, __nv_bfloat16* __restrict__ Tl_)
{
    extern __shared__ char smem_raw[];
    const unsigned sbase = smem_u32(smem_raw);
    const int tid = threadIdx.x;
    const int bid = blockIdx.x;
    const int wid = tid >> 5, lane = tid & 31;
    const int lmat = lane >> 3, lrow = lane & 7;
    const int a_m = (lmat & 1) * 8 + lrow, a_k = (lmat >> 1) * 8;
    const int b_n = (lmat >> 1) * 8 + lrow, b_k = (lmat & 1) * 8;

    if (bid < 256) {
        // ---------------- T branch: 64x64 complex 3M ----------------
        const int m = bid >> 6;
        const int row0 = ((bid >> 3) & 7) * 64;
        const int col0 = (bid & 7) * 64;
        const int warpM = (wid & 1) * 32, warpN = (wid >> 1) * 16;

        const size_t zBase = (size_t)m * 3 * DD;
        const __nv_bfloat16* aP[3][2];
        const __nv_bfloat16* bP[3][2];
#pragma unroll
        for (int c = 0; c < 3; c++) {
            aP[c][0] = Zh_ + zBase + (size_t)c * DD + (size_t)row0 * Dc;
            aP[c][1] = Zl_ + zBase + (size_t)c * DD + (size_t)row0 * Dc;
            bP[c][0] = WH + (size_t)(12 + m * 3 + c) * DD + (size_t)col0 * Dc;
            bP[c][1] = WL + (size_t)(12 + m * 3 + c) * DD + (size_t)col0 * Dc;
        }

        float acc[3][2][2][4];
#pragma unroll
        for (int p = 0; p < 3; p++)
#pragma unroll
            for (int mt = 0; mt < 2; mt++)
#pragma unroll
                for (int nt = 0; nt < 2; nt++)
#pragma unroll
                    for (int q = 0; q < 4; q++) acc[p][mt][nt][q] = 0.f;

        auto stage_load = [&](int ch, unsigned stg) {
            const int k0 = ch << 6;
#pragma unroll
            for (int c = 0; c < 3; c++)
#pragma unroll
                for (int hl = 0; hl < 2; hl++) {
                    unsigned tOff = (unsigned)((c * 2 + hl) * 8192);
#pragma unroll
                    for (int it = 0; it < 2; it++) {
                        int idx = it * 256 + tid;
                        int r = idx >> 3, cc = (idx & 7) * 8;
                        unsigned so = swz128((unsigned)(r * 128 + cc * 2));
                        cpasync16(stg + tOff + so, aP[c][hl] + (size_t)r * Dc + k0 + cc);
                        cpasync16(stg + 49152u + tOff + so, bP[c][hl] + (size_t)r * Dc + k0 + cc);
                    }
                }
            cp_commit();
        };
        auto compute = [&](unsigned stg) {
#pragma unroll
            for (int ks = 0; ks < 4; ks++) {
                unsigned afh[3][2][4], afl[3][2][4];
#pragma unroll
                for (int c = 0; c < 3; c++)
#pragma unroll
                    for (int mt = 0; mt < 2; mt++) {
                        int mm = warpM + mt * 16 + a_m;
                        unsigned off = swz128((unsigned)(mm * 128 + (ks * 16 + a_k) * 2));
                        ldmat_x4(afh[c][mt], stg + (unsigned)((c * 2 + 0) * 8192) + off);
                        ldmat_x4(afl[c][mt], stg + (unsigned)((c * 2 + 1) * 8192) + off);
                    }
                unsigned bfh[3][2][2], bfl[3][2][2];
#pragma unroll
                for (int c = 0; c < 3; c++) {
                    int n = warpN + b_n;
                    unsigned off = swz128((unsigned)(n * 128 + (ks * 16 + b_k) * 2));
                    unsigned rh[4], rl[4];
                    ldmat_x4(rh, stg + 49152u + (unsigned)((c * 2 + 0) * 8192) + off);
                    ldmat_x4(rl, stg + 49152u + (unsigned)((c * 2 + 1) * 8192) + off);
                    bfh[c][0][0] = rh[0]; bfh[c][0][1] = rh[1];
                    bfh[c][1][0] = rh[2]; bfh[c][1][1] = rh[3];
                    bfl[c][0][0] = rl[0]; bfl[c][0][1] = rl[1];
                    bfl[c][1][0] = rl[2]; bfl[c][1][1] = rl[3];
                }
#pragma unroll
                for (int p = 0; p < 3; p++)
#pragma unroll
                    for (int mt = 0; mt < 2; mt++)
#pragma unroll
                        for (int nt = 0; nt < 2; nt++) {
                            mma16816(acc[p][mt][nt], afh[p][mt], bfh[p][nt]);
                            mma16816(acc[p][mt][nt], afh[p][mt], bfl[p][nt]);
                            mma16816(acc[p][mt][nt], afl[p][mt], bfh[p][nt]);
                        }
            }
        };

        const unsigned stg0 = sbase, stg1 = sbase + (unsigned)STAGE3M;
        const int nchunk = 8;
        stage_load(0, stg0);
        for (int ch = 0; ch < nchunk; ch++) {
            unsigned cur = (ch & 1) ? stg1 : stg0;
            if (ch + 1 < nchunk) { stage_load(ch + 1, (ch & 1) ? stg0 : stg1); cp_wait<1>(); }
            else cp_wait<0>();
            __syncthreads();
            compute(cur);
            __syncthreads();
        }

        const int erow = lane >> 2, ecol = (lane & 3) * 2;
#pragma unroll
        for (int mt = 0; mt < 2; mt++)
#pragma unroll
            for (int nt = 0; nt < 2; nt++)
#pragma unroll
                for (int half = 0; half < 2; half++) {
                    int rowG = row0 + warpM + mt * 16 + erow + half * 8;
                    int colG = col0 + warpN + nt * 8 + ecol;   // complex col
                    float m1a = acc[0][mt][nt][half * 2],     m1b = acc[0][mt][nt][half * 2 + 1];
                    float m2a = acc[1][mt][nt][half * 2],     m2b = acc[1][mt][nt][half * 2 + 1];
                    float m3a = acc[2][mt][nt][half * 2],     m3b = acc[2][mt][nt][half * 2 + 1];
                    float tr0 = m1a - m2a,       tr1 = m1b - m2b;
                    float ti0 = m3a - m1a - m2a, ti1 = m3b - m1b - m2b;
                    size_t base = (size_t)m * (ROWS * E2) + (size_t)rowG * E2 + colG;
                    *(unsigned*)(Th_ + base) = pkbf2(tr0, tr1);
                    *(unsigned*)(Tl_ + base) = pkbf2(bflo(tr0), bflo(tr1));
                    *(unsigned*)(Th_ + base + Dc) = pkbf2(ti0, ti1);
                    *(unsigned*)(Tl_ + base + Dc) = pkbf2(bflo(ti0), bflo(ti1));
                }
    } else {
        // ---------------- V branch: 64x32 complex 3M ----------------
        const int vb = bid - 256;
        const int m = vb >> 7;
        const int row0 = ((vb >> 4) & 7) * 64;
        const int col0 = (vb & 15) * 32;     // complex col
        const int warpM = (wid & 3) * 16, warpN = (wid >> 2) * 16;

        const size_t zBase = (size_t)m * 3 * DD;
        const __nv_bfloat16* aP[3][2];
        const __nv_bfloat16* bP[3][2];
#pragma unroll
        for (int c = 0; c < 3; c++) {
            aP[c][0] = Zh_ + zBase + (size_t)c * DD + (size_t)row0 * Dc;
            aP[c][1] = Zl_ + zBase + (size_t)c * DD + (size_t)row0 * Dc;
            bP[c][0] = WH + (size_t)(36 + m * 3 + c) * DD + (size_t)col0 * Dc;
            bP[c][1] = WL + (size_t)(36 + m * 3 + c) * DD + (size_t)col0 * Dc;
        }

        float acc[3][2][4];                 // [p][nt][4], single mt
#pragma unroll
        for (int p = 0; p < 3; p++)
#pragma unroll
            for (int nt = 0; nt < 2; nt++)
#pragma unroll
                for (int q = 0; q < 4; q++) acc[p][nt][q] = 0.f;

        auto stage_load = [&](int ch, unsigned stg) {
            const int k0 = ch << 6;
#pragma unroll
            for (int c = 0; c < 3; c++)
#pragma unroll
                for (int hl = 0; hl < 2; hl++) {
                    unsigned aOff = (unsigned)((c * 2 + hl) * 8192);
#pragma unroll
                    for (int it = 0; it < 2; it++) {
                        int idx = it * 256 + tid;
                        int r = idx >> 3, cc = (idx & 7) * 8;
                        unsigned so = swz128((unsigned)(r * 128 + cc * 2));
                        cpasync16(stg + aOff + so, aP[c][hl] + (size_t)r * Dc + k0 + cc);
                    }
                    // B tile 32 rows x 64 K (4KB)
                    unsigned bOff = 49152u + (unsigned)((c * 2 + hl) * 4096);
                    int r = tid >> 3, cc = (tid & 7) * 8;
                    unsigned so = swz128((unsigned)(r * 128 + cc * 2));
                    cpasync16(stg + bOff + so, bP[c][hl] + (size_t)r * Dc + k0 + cc);
                }
            cp_commit();
        };
        auto compute = [&](unsigned stg) {
#pragma unroll
            for (int ks = 0; ks < 4; ks++) {
                unsigned afh[3][4], afl[3][4];
#pragma unroll
                for (int c = 0; c < 3; c++) {
                    int mm = warpM + a_m;
                    unsigned off = swz128((unsigned)(mm * 128 + (ks * 16 + a_k) * 2));
                    ldmat_x4(afh[c], stg + (unsigned)((c * 2 + 0) * 8192) + off);
                    ldmat_x4(afl[c], stg + (unsigned)((c * 2 + 1) * 8192) + off);
                }
                unsigned bfh[3][2][2], bfl[3][2][2];
#pragma unroll
                for (int c = 0; c < 3; c++) {
                    int n = warpN + b_n;
                    unsigned off = swz128((unsigned)(n * 128 + (ks * 16 + b_k) * 2));
                    unsigned rh[4], rl[4];
                    ldmat_x4(rh, stg + 49152u + (unsigned)((c * 2 + 0) * 4096) + off);
                    ldmat_x4(rl, stg + 49152u + (unsigned)((c * 2 + 1) * 4096) + off);
                    bfh[c][0][0] = rh[0]; bfh[c][0][1] = rh[1];
                    bfh[c][1][0] = rh[2]; bfh[c][1][1] = rh[3];
                    bfl[c][0][0] = rl[0]; bfl[c][0][1] = rl[1];
                    bfl[c][1][0] = rl[2]; bfl[c][1][1] = rl[3];
                }
#pragma unroll
                for (int p = 0; p < 3; p++)
#pragma unroll
                    for (int nt = 0; nt < 2; nt++) {
                        mma16816(acc[p][nt], afh[p], bfh[p][nt]);
                        mma16816(acc[p][nt], afh[p], bfl[p][nt]);
                        mma16816(acc[p][nt], afl[p], bfh[p][nt]);
                    }
            }
        };

        const unsigned stg0 = sbase, stg1 = sbase + (unsigned)STAGEVS;
        const int nchunk = 8;
        stage_load(0, stg0);
        for (int ch = 0; ch < nchunk; ch++) {
            unsigned cur = (ch & 1) ? stg1 : stg0;
            if (ch + 1 < nchunk) { stage_load(ch + 1, (ch & 1) ? stg0 : stg1); cp_wait<1>(); }
            else cp_wait<0>();
            __syncthreads();
            compute(cur);
            __syncthreads();
        }

        const int erow = lane >> 2, ecol = (lane & 3) * 2;
#pragma unroll
        for (int nt = 0; nt < 2; nt++)
#pragma unroll
            for (int half = 0; half < 2; half++) {
                int rowG = row0 + warpM + erow + half * 8;
                int colG = col0 + warpN + nt * 8 + ecol;
                float m1a = acc[0][nt][half * 2],     m1b = acc[0][nt][half * 2 + 1];
                float m2a = acc[1][nt][half * 2],     m2b = acc[1][nt][half * 2 + 1];
                float m3a = acc[2][nt][half * 2],     m3b = acc[2][nt][half * 2 + 1];
                float yr0 = m1a - m2a,       yr1 = m1b - m2b;
                float yi0 = m3a - m1a - m2a, yi1 = m3b - m1b - m2b;
                const int b = rowG >> 7, s = rowG & 127;
                size_t o = ((size_t)(m * 4 + b) * E2 + colG) * Sc + s;
                g_Vth[o] = __float2bfloat16(yr0);
                g_Vtl[o] = __float2bfloat16(bflo(yr0));
                g_Vth[o + Sc] = __float2bfloat16(yr1);
                g_Vtl[o + Sc] = __float2bfloat16(bflo(yr1));
                size_t oi = o + (size_t)Dc * Sc;
                g_Vth[oi] = __float2bfloat16(yi0);
                g_Vtl[oi] = __float2bfloat16(bflo(yi0));
                g_Vth[oi + Sc] = __float2bfloat16(yi1);
                g_Vtl[oi + Sc] = __float2bfloat16(bflo(yi1));
            }
    }
}

// ---------------------------------------------------------------------------
// QK logits GEMM: split-K atomic, B from Z planes (K-concat). grid (1,8,16).
// ---------------------------------------------------------------------------
__global__ void __launch_bounds__(256, 1) gemm_qk(
    const __nv_bfloat16* __restrict__ Ah, const __nv_bfloat16* __restrict__ Al,
    const __nv_bfloat16* __restrict__ Bh, const __nv_bfloat16* __restrict__ Bl,
    float* __restrict__ outF)
{
    extern __shared__ char smem_raw[];
    const unsigned sbase = smem_u32(smem_raw);
    const int tid = threadIdx.x, lane = tid & 31;
    const int z = blockIdx.z;
    const int kbase = blockIdx.y * 128;
    MmaCtx cx = make_ctx(tid);

    const __nv_bfloat16* aPh = Ah + (size_t)z * (Sc * E2) + kbase;
    const __nv_bfloat16* aPl = Al + (size_t)z * (Sc * E2) + kbase;
    const int m_ = z >> 2, b_ = z & 3;
    const int pl = kbase >> 9;
    const size_t boff = (size_t)(m_ * 3 + pl) * DD + (size_t)(b_ * 128) * 512 + (kbase & 511);
    const __nv_bfloat16* bPh = Bh + boff;
    const __nv_bfloat16* bPl = Bl + boff;

    float acc[2][8][4];
#pragma unroll
    for (int mt = 0; mt < 2; mt++)
#pragma unroll
        for (int nt = 0; nt < 8; nt++)
#pragma unroll
            for (int q = 0; q < 4; q++) acc[mt][nt][q] = 0.f;

    auto stg = [&](int i) { return sbase + (unsigned)((i % 3) * 65536); };
    mma_stage_load(tid, stg(0), 0, aPh, aPl, E2, bPh, bPl, 512);
    mma_stage_load(tid, stg(1), 64, aPh, aPl, E2, bPh, bPl, 512);
    cp_wait<1>();
    __syncthreads();
    mma_compute(cx, stg(0), acc);
    __syncthreads();
    cp_wait<0>();
    __syncthreads();
    mma_compute(cx, stg(1), acc);

    const int erow = lane >> 2, ecol = (lane & 3) * 2;
#pragma unroll
    for (int mt = 0; mt < 2; mt++)
#pragma unroll
        for (int nt = 0; nt < 8; nt++) {
            const float* c = acc[mt][nt];
#pragma unroll
            for (int half = 0; half < 2; half++) {
                int rowG = cx.warpM + mt * 16 + erow + half * 8;
                int colG = cx.warpN + nt * 8 + ecol;
                float* o = outF + (size_t)z * (Sc * Sc) + (size_t)rowG * Sc + colG;
                atomicAdd(o + 0, c[half * 2 + 0]);
                atomicAdd(o + 1, c[half * 2 + 1]);
            }
        }
}

// ---------------------------------------------------------------------------
// AV GEMM with FUSED softmax. grid (8, 1, 16).
// ---------------------------------------------------------------------------
__global__ void __launch_bounds__(256, 1) gemm_avsm(
    const __nv_bfloat16* __restrict__ Vth_, const __nv_bfloat16* __restrict__ Vtl_,
    float* __restrict__ P_,
    const float* __restrict__ score_w, const float* __restrict__ conf_w,
    const float* __restrict__ halt_w)
{
    extern __shared__ char smem_raw[];
    const unsigned sbase = smem_u32(smem_raw);
    float* slog = (float*)(smem_raw + 131072);
    const int tid = threadIdx.x;
    const int wid = tid >> 5, lane = tid & 31;
    const int z = blockIdx.z;
    const int col0 = blockIdx.x * 128;
    MmaCtx cx = make_ctx(tid);

    const __nv_bfloat16* bH = Vth_ + (size_t)z * (E2 * Sc) + (size_t)col0 * Sc;
    const __nv_bfloat16* bL = Vtl_ + (size_t)z * (E2 * Sc) + (size_t)col0 * Sc;
    stage_load_B(tid, sbase, 0, bH, bL, Sc);
    stage_load_B(tid, sbase + 65536u, 64, bH, bL, Sc);

    const float4* lg4 = (const float4*)(g_logits + (size_t)z * (Sc * Sc));
    float4* slog4 = (float4*)slog;
#pragma unroll
    for (int i = 0; i < 16; i++) slog4[i * 256 + tid] = lg4[i * 256 + tid];
    __syncthreads();

#pragma unroll
    for (int i = 0; i < 16; i++) {
        int row = (wid << 4) + i;
        float4 v4 = *(const float4*)(slog + row * 128 + lane * 4);
        float v0 = v4.x * SCALEF, v1 = v4.y * SCALEF, v2 = v4.z * SCALEF, v3 = v4.w * SCALEF;
        float mx = fmaxf(fmaxf(v0, v1), fmaxf(v2, v3));
#pragma unroll
        for (int o = 16; o; o >>= 1) mx = fmaxf(mx, __shfl_xor_sync(0xffffffffu, mx, o));
        float e0 = expf(v0 - mx), e1 = expf(v1 - mx), e2 = expf(v2 - mx), e3 = expf(v3 - mx);
        float su = e0 + e1 + e2 + e3;
#pragma unroll
        for (int o = 16; o; o >>= 1) su += __shfl_xor_sync(0xffffffffu, su, o);
        float inv = 1.f / su;
        float a0 = e0 * inv, a1 = e1 * inv, a2 = e2 * inv, a3 = e3 * inv;
        unsigned chOff = (lane >> 4) ? 65536u : 0u;
        unsigned so = swz128((unsigned)(row * 128 + (lane & 15) * 8));
        *(unsigned*)(smem_raw + chOff + so)         = pkbf2(a0, a1);
        *(unsigned*)(smem_raw + chOff + so + 4)     = pkbf2(a2, a3);
        *(unsigned*)(smem_raw + chOff + 16384 + so)     = pkbf2(bflo(a0), bflo(a1));
        *(unsigned*)(smem_raw + chOff + 16384 + so + 4) = pkbf2(bflo(a2), bflo(a3));
    }

    float acc[2][8][4];
#pragma unroll
    for (int mt = 0; mt < 2; mt++)
#pragma unroll
        for (int nt = 0; nt < 8; nt++)
#pragma unroll
            for (int q = 0; q < 4; q++) acc[mt][nt][q] = 0.f;

    cp_wait<1>();
    __syncthreads();
    mma_compute(cx, sbase, acc);
    cp_wait<0>();
    __syncthreads();
    mma_compute(cx, sbase + 65536u, acc);

    const int erow = lane >> 2, ecol = (lane & 3) * 2;
    const int m = z >> 2;
    float dots[2][2][3];
#pragma unroll
    for (int mt = 0; mt < 2; mt++)
#pragma unroll
        for (int half = 0; half < 2; half++)
#pragma unroll
            for (int j = 0; j < 3; j++) dots[mt][half][j] = 0.f;
#pragma unroll
    for (int mt = 0; mt < 2; mt++)
#pragma unroll
        for (int nt = 0; nt < 8; nt++) {
            float* c = acc[mt][nt];
#pragma unroll
            for (int half = 0; half < 2; half++) {
                int rowG = cx.warpM + mt * 16 + erow + half * 8;
                int colG = col0 + cx.warpN + nt * 8 + ecol;
                float v0 = c[half * 2 + 0], v1 = c[half * 2 + 1];
                int d0 = colG & 511, d1 = (colG + 1) & 511;
                v0 *= g_gate[m * Dc + d0];
                v1 *= g_gate[m * Dc + d1];
                dots[mt][half][0] += v0 * score_w[m * E2 + colG] + v1 * score_w[m * E2 + colG + 1];
                dots[mt][half][1] += v0 * conf_w[m * E2 + colG]  + v1 * conf_w[m * E2 + colG + 1];
                dots[mt][half][2] += v0 * halt_w[m * E2 + colG]  + v1 * halt_w[m * E2 + colG + 1];
                float* o = P_ + (size_t)z * (Sc * E2) + (size_t)rowG * E2 + colG;
                o[0] = v0; o[1] = v1;
            }
        }
#pragma unroll
    for (int mt = 0; mt < 2; mt++)
#pragma unroll
        for (int half = 0; half < 2; half++) {
#pragma unroll
            for (int j = 0; j < 3; j++) {
                dots[mt][half][j] += __shfl_xor_sync(0xffffffffu, dots[mt][half][j], 1);
                dots[mt][half][j] += __shfl_xor_sync(0xffffffffu, dots[mt][half][j], 2);
            }
            if ((lane & 3) == 0) {
                int rowG = cx.warpM + mt * 16 + erow + half * 8;
                int srow = z * Sc + rowG;
                atomicAdd(&g_score[srow], dots[mt][half][0]);
                atomicAdd(&g_conf[srow],  dots[mt][half][1]);
                atomicAdd(&g_halt[srow],  dots[mt][half][2]);
            }
        }
}

// ---------------------------------------------------------------------------
// one-time H^T GEMM: z = m*3+comp; C[d'][d] = sum_e Ak[m][d'][e]*Aq_c[m][d][e]
// writes split-bf16 into WP plane 12+z. grid (4,4,12).
// ---------------------------------------------------------------------------
__global__ void __launch_bounds__(256, 1) gemm_H(
    const __nv_bfloat16* __restrict__ ABh_, const __nv_bfloat16* __restrict__ ABl_,
    __nv_bfloat16* __restrict__ WPh_, __nv_bfloat16* __restrict__ WPl_)
{
    extern __shared__ char smem_raw[];
    const unsigned sbase = smem_u32(smem_raw);
    const int tid = threadIdx.x, lane = tid & 31;
    const int z = blockIdx.z;
    const int m = z / 3, comp = z % 3;
    const int col0 = blockIdx.x * 128, row0 = blockIdx.y * 128;
    MmaCtx cx = make_ctx(tid);

    const size_t akBase = (size_t)m * (512 * 1024);
    const size_t aqBase = (size_t)(1 + comp) * 2 * MM + (size_t)m * (512 * 1024);
    const __nv_bfloat16* aPh = ABh_ + akBase + (size_t)row0 * 1024;
    const __nv_bfloat16* aPl = ABl_ + akBase + (size_t)row0 * 1024;
    const __nv_bfloat16* bPh = ABh_ + aqBase + (size_t)col0 * 1024;
    const __nv_bfloat16* bPl = ABl_ + aqBase + (size_t)col0 * 1024;

    float acc[2][8][4];
#pragma unroll
    for (int mt = 0; mt < 2; mt++)
#pragma unroll
        for (int nt = 0; nt < 8; nt++)
#pragma unroll
            for (int q = 0; q < 4; q++) acc[mt][nt][q] = 0.f;

    const int nchunk = 16;
    auto stg = [&](int i) { return sbase + (unsigned)((i % 3) * 65536); };
    mma_stage_load(tid, stg(0), 0, aPh, aPl, 1024, bPh, bPl, 1024);
    mma_stage_load(tid, stg(1), 64, aPh, aPl, 1024, bPh, bPl, 1024);
    for (int ch = 0; ch < nchunk; ch++) {
        if (ch + 2 < nchunk) {
            mma_stage_load(tid, stg(ch + 2), (ch + 2) << 6, aPh, aPl, 1024, bPh, bPl, 1024);
            cp_wait<2>();
        } else if (ch + 1 < nchunk) cp_wait<1>();
        else cp_wait<0>();
        __syncthreads();
        mma_compute(cx, stg(ch), acc);
        __syncthreads();
    }

    const int erow = lane >> 2, ecol = (lane & 3) * 2;
#pragma unroll
    for (int mt = 0; mt < 2; mt++)
#pragma unroll
        for (int nt = 0; nt < 8; nt++) {
            const float* c = acc[mt][nt];
#pragma unroll
            for (int half = 0; half < 2; half++) {
                int rowG = row0 + cx.warpM + mt * 16 + erow + half * 8;
                int colG = col0 + cx.warpN + nt * 8 + ecol;
                float v0 = c[half * 2 + 0], v1 = c[half * 2 + 1];
                size_t base = (size_t)(12 + z) * DD + (size_t)rowG * 512 + colG;
                *(unsigned*)(WPh_ + base) = pkbf2(v0, v1);
                *(unsigned*)(WPl_ + base) = pkbf2(bflo(v0), bflo(v1));
            }
        }
}

// ---------------------------------------------------------------------------
// small kernels
// ---------------------------------------------------------------------------
// Wl planes (0..11) and Wv planes (36..47)
__global__ void k_pack(const float* __restrict__ Wl_r, const float* __restrict__ Wl_i,
                       const float* __restrict__ Wv_r, const float* __restrict__ Wv_i) {
    size_t idx = (size_t)blockIdx.x * 256 + threadIdx.x;   // 24 * 2^18
    int p24 = (int)(idx >> 18);
    int r = (int)(idx & (DD - 1));
    int ty2 = p24 / 12, rem = p24 % 12, m = rem / 3, comp = rem % 3;
    const float* Wr = ty2 ? Wv_r : Wl_r;
    const float* Wi = ty2 ? Wv_i : Wl_i;
    size_t base = (size_t)m * DD + r;
    float v = (comp == 0) ? Wr[base] : (comp == 1) ? Wi[base] : (Wr[base] + Wi[base]);
    size_t out = (size_t)((ty2 ? 36 : 0) + rem) * DD + r;
    g_WPH[out] = __float2bfloat16(v);
    g_WPL[out] = __float2bfloat16(bflo(v));
}

// Ak [m][d][e1024] = [WkR[o][d] | WkI[o][d]] ; Aq planes:
// p0=[WqR|WqI], p1=[WqI|-WqR], p2=[WqR+WqI | WqI-WqR]. g = idx>>21.
__global__ void k_packQK(const float* __restrict__ Wq_r, const float* __restrict__ Wq_i,
                         const float* __restrict__ Wk_r, const float* __restrict__ Wk_i) {
    size_t idx = (size_t)blockIdx.x * 256 + threadIdx.x;   // 8 * 2^20
    int g = (int)(idx >> 21);
    int m = (int)((idx >> 19) & 3);
    int d = (int)((idx >> 10) & 511);
    int e = (int)(idx & 1023);
    int o = e & 511;
    bool hi = e >= 512;
    size_t w = (size_t)m * DD + (size_t)o * Dc + d;
    float v;
    if (g == 0)      v = hi ?  Wk_i[w] : Wk_r[w];
    else if (g == 1) v = hi ?  Wq_i[w] : Wq_r[w];
    else if (g == 2) v = hi ? -Wq_r[w] : Wq_i[w];
    else             v = hi ? (Wq_i[w] - Wq_r[w]) : (Wq_r[w] + Wq_i[w]);
    g_ABh[idx] = __float2bfloat16(v);
    g_ABl[idx] = __float2bfloat16(bflo(v));
}

__global__ void k_init(const float* __restrict__ xr, const float* __restrict__ xi,
                       const float* __restrict__ gate_mask) {
    int i = blockIdx.x * 256 + threadIdx.x;
    if (i < ROWS * Dc) {
        g_sr[i] = xr[i]; g_si[i] = xi[i];
        float cr = xr[i], ci = xi[i], cs = cr + ci;
        g_Ch[i] = __float2bfloat16(cr);          g_Cl[i] = __float2bfloat16(bflo(cr));
        g_Ch[DD + i] = __float2bfloat16(ci);     g_Cl[DD + i] = __float2bfloat16(bflo(ci));
        g_Ch[2 * DD + i] = __float2bfloat16(cs); g_Cl[2 * DD + i] = __float2bfloat16(bflo(cs));
    }
    if (i < ROWS * E2) g_acc[i] = 0.f;
    if (i < 16 * Sc * Sc) g_logits[i] = 0.f;
    if (i < NMBS) { g_score[i] = 0.f; g_conf[i] = 0.f; g_halt[i] = 0.f; }
    if (i < Bc * Kc * E2) g_mem[i] = 0.f;
    if (i < Bc * Kc) g_ptrst[i] = (i % Kc == 0) ? 1.f : 0.f;
    if (i < Mc * Dc) g_gate[i] = sigm(gate_mask[i]);
    if (i < Bc) g_rem[i] = 1.f;
    if (i < Bc * E2) {
        int b = i >> 10, e = i & 1023;
        const float* base = (e < Dc) ? (xr + (size_t)b * Sc * Dc + e)
                                     : (xi + (size_t)b * Sc * Dc + (e - Dc));
        float s = 0.f;
#pragma unroll 4
        for (int ss = 0; ss < Sc; ss++) s += base[(size_t)ss * Dc];
        g_flat[i] = s * (1.f / Sc);
    }
}

__global__ void k_norm(const float* __restrict__ ln_scale,
                       const float* __restrict__ ln_shift,
                       const float* __restrict__ mod_bias) {
    const int row = blockIdx.x;
    const int m = row >> 9, bs = row & 511;
    const float* zp = g_Z + (size_t)row * E2;
    const int t = threadIdx.x;
    float4 r4 = *(const float4*)(zp + 4 * t);
    float4 i4 = *(const float4*)(zp + Dc + 4 * t);
    float vr[4] = {r4.x, r4.y, r4.z, r4.w};
    float vi[4] = {i4.x, i4.y, i4.z, i4.w};
    float mg[4];
    float s = 0.f, ss = 0.f;
#pragma unroll
    for (int q = 0; q < 4; q++) {
        mg[q] = sqrtf(vr[q] * vr[q] + vi[q] * vi[q]) + EPSF;
        s += mg[q]; ss += mg[q] * mg[q];
    }
    float sum = blockSum128(s);
    float sumsq = blockSum128(ss);
    float mean = sum * (1.f / Dc);
    float var = (sumsq - (float)Dc * mean * mean) * (1.f / (Dc - 1));
    float rstd = rsqrtf(var + EPSF);
    float4 lsc = *(const float4*)(ln_scale + m * Dc + 4 * t);
    float4 lsh = *(const float4*)(ln_shift + m * Dc + 4 * t);
    float4 mb  = *(const float4*)(mod_bias + m * Dc + 4 * t);
    float lscv[4] = {lsc.x, lsc.y, lsc.z, lsc.w};
    float lshv[4] = {lsh.x, lsh.y, lsh.z, lsh.w};
    float mbv[4]  = {mb.x, mb.y, mb.z, mb.w};
    float fr[4], fi[4], fs[4];
#pragma unroll
    for (int q = 0; q < 4; q++) {
        float nm = (mg[q] - mean) * rstd * lscv[q] + lshv[q];
        float hyp = mg[q] - EPSF;
        float c, sn;
        if (hyp > 0.f) { float ih = 1.f / hyp; c = vr[q] * ih; sn = vi[q] * ih; }
        else { c = 1.f; sn = 0.f; }
        float zr2 = nm * c, zi2 = nm * sn;
        float nrm = fabsf(nm) + EPSF;
        float sc = fmaxf(nrm + mbv[q], 0.f) / nrm;
        fr[q] = zr2 * sc; fi[q] = zi2 * sc; fs[q] = fr[q] + fi[q];
    }
    const size_t off = (size_t)bs * Dc + 4 * t;
    __nv_bfloat16* oh0 = g_Zh + (size_t)(m * 3 + 0) * DD + off;
    __nv_bfloat16* ol0 = g_Zl + (size_t)(m * 3 + 0) * DD + off;
    *(uint2*)oh0 = make_uint2(pkbf2(fr[0], fr[1]), pkbf2(fr[2], fr[3]));
    *(uint2*)ol0 = make_uint2(pkbf2(bflo(fr[0]), bflo(fr[1])), pkbf2(bflo(fr[2]), bflo(fr[3])));
    __nv_bfloat16* oh1 = g_Zh + (size_t)(m * 3 + 1) * DD + off;
    __nv_bfloat16* ol1 = g_Zl + (size_t)(m * 3 + 1) * DD + off;
    *(uint2*)oh1 = make_uint2(pkbf2(fi[0], fi[1]), pkbf2(fi[2], fi[3]));
    *(uint2*)ol1 = make_uint2(pkbf2(bflo(fi[0]), bflo(fi[1])), pkbf2(bflo(fi[2]), bflo(fi[3])));
    __nv_bfloat16* oh2 = g_Zh + (size_t)(m * 3 + 2) * DD + off;
    __nv_bfloat16* ol2 = g_Zl + (size_t)(m * 3 + 2) * DD + off;
    *(uint2*)oh2 = make_uint2(pkbf2(fs[0], fs[1]), pkbf2(fs[2], fs[3]));
    *(uint2*)ol2 = make_uint2(pkbf2(bflo(fs[0]), bflo(fs[1])), pkbf2(bflo(fs[2]), bflo(fs[3])));
}

__global__ void k_stack(const float* __restrict__ cw,  const float* __restrict__ cb,
                        const float* __restrict__ stw, const float* __restrict__ stb,
                        const float* __restrict__ scw, const float* __restrict__ scb,
                        const float* __restrict__ halt_b) {
    __shared__ float s_red[8];
    __shared__ float s_ptr[Kc], s_wmask[Kc];
    const int b = blockIdx.x, t = threadIdx.x;
    const int e0 = 4 * t;

    float4 fv = *(float4*)(g_flat + b * E2 + e0);
    *(float4*)(g_flat + b * E2 + e0) = make_float4(0.f, 0.f, 0.f, 0.f);

    float a0 = fv.x * cw[e0 * 3]     + fv.y * cw[(e0 + 1) * 3]     + fv.z * cw[(e0 + 2) * 3]     + fv.w * cw[(e0 + 3) * 3];
    float a1 = fv.x * cw[e0 * 3 + 1] + fv.y * cw[(e0 + 1) * 3 + 1] + fv.z * cw[(e0 + 2) * 3 + 1] + fv.w * cw[(e0 + 3) * 3 + 1];
    float a2 = fv.x * cw[e0 * 3 + 2] + fv.y * cw[(e0 + 1) * 3 + 2] + fv.z * cw[(e0 + 2) * 3 + 2] + fv.w * cw[(e0 + 3) * 3 + 2];
    a0 = blockSum256(a0, s_red); a1 = blockSum256(a1, s_red); a2 = blockSum256(a2, s_red);
    a0 += cb[0]; a1 += cb[1]; a2 += cb[2];
    float mx3 = fmaxf(a0, fmaxf(a1, a2));
    float e0e = expf(a0 - mx3), e1e = expf(a1 - mx3), e2e = expf(a2 - mx3);
    float is3 = 1.f / (e0e + e1e + e2e);
    float push = e0e * is3, pop = e1e * is3, noop = e2e * is3;

    if (t < Kc) {
        float* P = g_ptrst + b * Kc;
        float pu = P[(t + Kc - 1) % Kc];
        float pd = P[(t + 1) % Kc];
        float pc = P[t];
        float np = push * pu + pop * pd + noop * pc;
        float s = np;
#pragma unroll
        for (int o = 16; o; o >>= 1) s += __shfl_xor_sync(0xffffffffu, s, o);
        np /= (s + EPSF);
        P[t] = np;
        s_ptr[t] = np;
        s_wmask[t] = push * pu;
    }
    __syncthreads();

    float4 racc = make_float4(0.f, 0.f, 0.f, 0.f);
#pragma unroll
    for (int k = 0; k < Kc; k++) {
        float w = s_wmask[k], pk = s_ptr[k];
        float4* mp = (float4*)(g_mem + ((size_t)(b * Kc + k)) * E2 + e0);
        float4 old = *mp;
        float4 nm = make_float4(fmaf(w, fv.x - old.x, old.x), fmaf(w, fv.y - old.y, old.y),
                                fmaf(w, fv.z - old.z, old.z), fmaf(w, fv.w - old.w, old.w));
        *mp = nm;
        racc.x += nm.x * pk; racc.y += nm.y * pk; racc.z += nm.z * pk; racc.w += nm.w * pk;
    }
    *(float4*)(g_read + b * E2 + e0) = racc;
    float4 w1 = *(const float4*)(stw + e0);
    float4 w2 = *(const float4*)(scw + e0);
    float s1 = racc.x * w1.x + racc.y * w1.y + racc.z * w1.z + racc.w * w1.w;
    float s2 = racc.x * w2.x + racc.y * w2.y + racc.z * w2.z + racc.w * w2.w;
    float h = 0.f;
    for (int idx = t; idx < Mc * Sc; idx += 256) {
        int mIdx = idx >> 7;
        h += sigm(g_halt[mIdx * NBS + b * Sc + (idx & 127)] + halt_b[mIdx]);
    }
    s1 = blockSum256(s1, s_red); s2 = blockSum256(s2, s_red); h = blockSum256(h, s_red);
    if (t == 0) {
        g_stsc[b] = s1 + stb[0];
        g_stcf[b] = sigm(s2 + scb[0]);
        float p = h * (1.f / (Mc * Sc));
        float rm = g_rem[b];
        g_coef[b] = p * rm;
        g_rem[b] = rm * (1.f - p);
    }
}

// combine + state/acc + NEXT-step C + flat accum + logits & dot-buffer zero
__global__ void k_combine(const float* __restrict__ xr, const float* __restrict__ xi,
                          const float* __restrict__ score_b, const float* __restrict__ conf_b) {
    const int bs = blockIdx.x;
    const int b = bs >> 7;
    float l[5];
#pragma unroll
    for (int m = 0; m < Mc; m++) {
        float sA = g_score[m * NBS + bs] + score_b[m];
        float cA = sigm(g_conf[m * NBS + bs] + conf_b[m]);
        l[m] = sA * cA;
    }
    l[4] = g_stsc[b] * g_stcf[b];
    __syncthreads();
    if (threadIdx.x == 0) {
#pragma unroll
        for (int m = 0; m < Mc; m++) {
            g_score[m * NBS + bs] = 0.f;
            g_conf[m * NBS + bs] = 0.f;
            g_halt[m * NBS + bs] = 0.f;
        }
    }
    float mx = l[0];
#pragma unroll
    for (int m = 1; m < 5; m++) mx = fmaxf(mx, l[m]);
    float w[5], s = 0.f;
#pragma unroll
    for (int m = 0; m < 5; m++) { w[m] = expf(l[m] - mx); s += w[m]; }
    float is = 1.f / s;
#pragma unroll
    for (int m = 0; m < 5; m++) w[m] *= is;
    float cf = g_coef[b];
    const int t = threadIdx.x;
    const int d0 = 4 * t;

    float4 rd = *(const float4*)(g_read + b * E2 + d0);
    float4 ri = *(const float4*)(g_read + b * E2 + Dc + d0);
    float nr[4] = {w[4] * rd.x, w[4] * rd.y, w[4] * rd.z, w[4] * rd.w};
    float ni[4] = {w[4] * ri.x, w[4] * ri.y, w[4] * ri.z, w[4] * ri.w};
#pragma unroll
    for (int m = 0; m < Mc; m++) {
        const float* pb = g_P + ((size_t)m * NBS + bs) * E2;
        float4 pr = *(const float4*)(pb + d0);
        float4 pi = *(const float4*)(pb + Dc + d0);
        nr[0] += w[m] * pr.x; nr[1] += w[m] * pr.y; nr[2] += w[m] * pr.z; nr[3] += w[m] * pr.w;
        ni[0] += w[m] * pi.x; ni[1] += w[m] * pi.y; ni[2] += w[m] * pi.z; ni[3] += w[m] * pi.w;
    }
    *(float4*)(g_sr + (size_t)bs * Dc + d0) = make_float4(nr[0], nr[1], nr[2], nr[3]);
    *(float4*)(g_si + (size_t)bs * Dc + d0) = make_float4(ni[0], ni[1], ni[2], ni[3]);
    float4 a0 = *(float4*)(g_acc + (size_t)bs * E2 + d0);
    float4 a1 = *(float4*)(g_acc + (size_t)bs * E2 + Dc + d0);
    a0.x += cf * nr[0]; a0.y += cf * nr[1]; a0.z += cf * nr[2]; a0.w += cf * nr[3];
    a1.x += cf * ni[0]; a1.y += cf * ni[1]; a1.z += cf * ni[2]; a1.w += cf * ni[3];
    *(float4*)(g_acc + (size_t)bs * E2 + d0) = a0;
    *(float4*)(g_acc + (size_t)bs * E2 + Dc + d0) = a1;

    float4 x0 = *(const float4*)(xr + (size_t)bs * Dc + d0);
    float4 x1 = *(const float4*)(xi + (size_t)bs * Dc + d0);
    float cr[4] = {0.5f * (x0.x + nr[0]), 0.5f * (x0.y + nr[1]), 0.5f * (x0.z + nr[2]), 0.5f * (x0.w + nr[3])};
    float ci[4] = {0.5f * (x1.x + ni[0]), 0.5f * (x1.y + ni[1]), 0.5f * (x1.z + ni[2]), 0.5f * (x1.w + ni[3])};
    float cs[4] = {cr[0] + ci[0], cr[1] + ci[1], cr[2] + ci[2], cr[3] + ci[3]};
    const size_t co = (size_t)bs * Dc + d0;
    *(uint2*)(g_Ch + co) = make_uint2(pkbf2(cr[0], cr[1]), pkbf2(cr[2], cr[3]));
    *(uint2*)(g_Cl + co) = make_uint2(pkbf2(bflo(cr[0]), bflo(cr[1])), pkbf2(bflo(cr[2]), bflo(cr[3])));
    *(uint2*)(g_Ch + DD + co) = make_uint2(pkbf2(ci[0], ci[1]), pkbf2(ci[2], ci[3]));
    *(uint2*)(g_Cl + DD + co) = make_uint2(pkbf2(bflo(ci[0]), bflo(ci[1])), pkbf2(bflo(ci[2]), bflo(ci[3])));
    *(uint2*)(g_Ch + 2 * DD + co) = make_uint2(pkbf2(cs[0], cs[1]), pkbf2(cs[2], cs[3]));
    *(uint2*)(g_Cl + 2 * DD + co) = make_uint2(pkbf2(bflo(cs[0]), bflo(cs[1])), pkbf2(bflo(cs[2]), bflo(cs[3])));

    constexpr float invS = 1.f / Sc;
#pragma unroll
    for (int q = 0; q < 4; q++) {
        atomicAdd(g_flat + b * E2 + d0 + q, nr[q] * invS);
        atomicAdd(g_flat + b * E2 + Dc + d0 + q, ni[q] * invS);
    }
    *(float4*)(g_logits + (size_t)bs * 512 + d0) = make_float4(0.f, 0.f, 0.f, 0.f);
}

__global__ void k_final(float* __restrict__ out) {
    int i = blockIdx.x * 256 + threadIdx.x;
    int bs = i >> 10, e = i & 1023;
    int b = bs >> 7;
    float st = (e < Dc) ? g_sr[(size_t)bs * Dc + e]
                        : g_si[(size_t)bs * Dc + (e - Dc)];
    out[i] = g_acc[i] + g_rem[b] * st;
}

// ---------------------------------------------------------------------------
extern "C" void kernel_launch(void* const* d_in, const int* in_sizes, int n_in,
                              void* d_out, int out_size) {
    const float* xr        = (const float*)d_in[0];
    const float* xi        = (const float*)d_in[1];
    const float* Wl_r      = (const float*)d_in[2];
    const float* Wl_i      = (const float*)d_in[3];
    const float* Wq_r      = (const float*)d_in[4];
    const float* Wq_i      = (const float*)d_in[5];
    const float* Wk_r      = (const float*)d_in[6];
    const float* Wk_i      = (const float*)d_in[7];
    const float* Wv_r      = (const float*)d_in[8];
    const float* Wv_i      = (const float*)d_in[9];
    const float* ln_scale  = (const float*)d_in[10];
    const float* ln_shift  = (const float*)d_in[11];
    const float* mod_bias  = (const float*)d_in[12];
    const float* gate_mask = (const float*)d_in[13];
    const float* score_w   = (const float*)d_in[14];
    const float* score_b   = (const float*)d_in[15];
    const float* conf_w    = (const float*)d_in[16];
    const float* conf_b    = (const float*)d_in[17];
    const float* halt_w    = (const float*)d_in[18];
    const float* halt_b    = (const float*)d_in[19];
    const float* ctrl_w    = (const float*)d_in[20];
    const float* ctrl_b    = (const float*)d_in[21];
    const float* st_score_w= (const float*)d_in[22];
    const float* st_score_b= (const float*)d_in[23];
    const float* st_conf_w = (const float*)d_in[24];
    const float* st_conf_b = (const float*)d_in[25];

    cudaFuncSetAttribute(gemm_3m_wl, cudaFuncAttributeMaxDynamicSharedMemorySize, GEMM3M_SMEM);
    cudaFuncSetAttribute(gemm_TV,    cudaFuncAttributeMaxDynamicSharedMemorySize, GEMM3M_SMEM);
    cudaFuncSetAttribute(gemm_qk,    cudaFuncAttributeMaxDynamicSharedMemorySize, GEMM_SMEM);
    cudaFuncSetAttribute(gemm_avsm,  cudaFuncAttributeMaxDynamicSharedMemorySize, GEMM_SMEM);
    cudaFuncSetAttribute(gemm_H,     cudaFuncAttributeMaxDynamicSharedMemorySize, GEMM_SMEM);

    __nv_bfloat16 *WPH, *WPL, *ABh, *ABl, *Ch, *Cl, *Zh, *Zl, *Th, *Tl, *Vth, *Vtl;
    float *Z, *LG, *P;
    cudaGetSymbolAddress((void**)&WPH, g_WPH);
    cudaGetSymbolAddress((void**)&WPL, g_WPL);
    cudaGetSymbolAddress((void**)&ABh, g_ABh);
    cudaGetSymbolAddress((void**)&ABl, g_ABl);
    cudaGetSymbolAddress((void**)&Ch, g_Ch);
    cudaGetSymbolAddress((void**)&Cl, g_Cl);
    cudaGetSymbolAddress((void**)&Z,  g_Z);
    cudaGetSymbolAddress((void**)&Zh, g_Zh);
    cudaGetSymbolAddress((void**)&Zl, g_Zl);
    cudaGetSymbolAddress((void**)&Th, g_Th);
    cudaGetSymbolAddress((void**)&Tl, g_Tl);
    cudaGetSymbolAddress((void**)&Vth, g_Vth);
    cudaGetSymbolAddress((void**)&Vtl, g_Vtl);
    cudaGetSymbolAddress((void**)&LG, g_logits);
    cudaGetSymbolAddress((void**)&P, g_P);

    // one-time setup
    k_pack<<<24 * (DD / 256), 256>>>(Wl_r, Wl_i, Wv_r, Wv_i);
    k_packQK<<<32768, 256>>>(Wq_r, Wq_i, Wk_r, Wk_i);
    gemm_H<<<dim3(4, 4, 12), 256, GEMM_SMEM>>>(ABh, ABl, WPH, WPL);
    k_init<<<2048, 256>>>(xr, xi, gate_mask);

    for (int step = 0; step < NSTEPS; step++) {
        gemm_3m_wl<<<dim3(8, 8, Mc), 256, GEMM3M_SMEM>>>(Ch, Cl, WPH, WPL, Z);
        k_norm<<<NMBS, 128>>>(ln_scale, ln_shift, mod_bias);
        // fused T (Karatsuba, 256 blocks) + V (64x32 tiles, 512 blocks)
        gemm_TV<<<768, 256, GEMM3M_SMEM>>>(Zh, Zl, WPH, WPL, Th, Tl);
        // logits = T . zf^T (split-K=8)
        gemm_qk<<<dim3(1, 8, 16), 256, GEMM_SMEM>>>(Th, Tl, Zh, Zl, LG);
        // AV with fused softmax + gate + dots
        gemm_avsm<<<dim3(8, 1, 16), 256, GEMM_SMEM>>>(Vth, Vtl, P, score_w, conf_w, halt_w);
        k_stack<<<Bc, 256>>>(ctrl_w, ctrl_b, st_score_w, st_score_b, st_conf_w, st_conf_b, halt_b);
        k_combine<<<NBS, 128>>>(xr, xi, score_b, conf_b);
    }
    k_final<<<2048, 256>>>((float*)d_out);
}

// round 17
// speedup vs baseline: 1.0326x; 1.0326x over previous
#include <cuda_runtime.h>
#include <cuda_bf16.h>
#include <math.h>

// ---------------------------------------------------------------------------
// ComplexRecurrentModel on GB300 (sm_103 non-'a' PTX target).
// ROUND 17: T = z*H Karatsuba (verified round 16, -25% T MMAs) with V back
// on the proven 64x64 3M tiling -> TV launch is 512 UNIFORM 3M blocks
// sharing one code path (B plane base + epilogue differ).
// H = Wq^T conj(Wk) precomputed once (H^T comp planes r,i,r+i).
// ---------------------------------------------------------------------------

#define Bc 4
#define Sc 128
#define Dc 512
#define Mc 4
#define Kc 32
#define NSTEPS 16
#define EPSF 1e-6f
#define SCALEF 0.044194173824159216f   // 512^-0.5

constexpr int ROWS = Bc * Sc;              // 512
constexpr int E2 = 2 * Dc;                 // 1024
constexpr int NBS = Bc * Sc;               // 512
constexpr int NMBS = Mc * NBS;             // 2048
constexpr int DD = Dc * Dc;                // 262144
constexpr int WPLANES = 48;
constexpr size_t MM = (size_t)1 << 20;

// ---- device buffers -------------------------------------------------------
// WP planes: 0..11 Wl comps, 12..23 H^T comps (r,i,s per m), 36..47 Wv comps
__device__ __align__(256) __nv_bfloat16 g_WPH[(size_t)WPLANES * DD];
__device__ __align__(256) __nv_bfloat16 g_WPL[(size_t)WPLANES * DD];
__device__ __align__(256) __nv_bfloat16 g_ABh[8 * MM], g_ABl[8 * MM];  // Ak + 3 Aq planes
__device__ __align__(256) __nv_bfloat16 g_Ch[3 * DD], g_Cl[3 * DD];
__device__ __align__(256) float         g_Z [Mc * ROWS * E2];
__device__ __align__(256) __nv_bfloat16 g_Zh[12 * DD], g_Zl[12 * DD];
__device__ __align__(256) __nv_bfloat16 g_Th[Mc * ROWS * E2], g_Tl[Mc * ROWS * E2];
__device__ __align__(256) __nv_bfloat16 g_Vth[16 * E2 * Sc], g_Vtl[16 * E2 * Sc];
__device__ __align__(256) float         g_logits[16 * Sc * Sc];
__device__ __align__(256) float         g_P [Mc * ROWS * E2];
__device__ __align__(256) float g_sr[ROWS * Dc], g_si[ROWS * Dc];
__device__ __align__(256) float g_acc[ROWS * E2];
__device__ __align__(256) float g_mem[Bc * Kc * E2];
__device__ __align__(256) float g_ptrst[Bc * Kc];
__device__ __align__(256) float g_score[NMBS], g_conf[NMBS], g_halt[NMBS];
__device__ __align__(256) float g_flat[Bc * E2], g_read[Bc * E2];
__device__ __align__(256) float g_gate[Mc * Dc];
__device__ __align__(256) float g_rem[16], g_stsc[16], g_stcf[16], g_coef[16];

// ---------------------------------------------------------------------------
// helpers
// ---------------------------------------------------------------------------
__device__ __forceinline__ unsigned smem_u32(const void* p) {
    unsigned a;
    asm("{ .reg .u64 t; cvta.to.shared.u64 t, %1; cvt.u32.u64 %0, t; }" : "=r"(a) : "l"(p));
    return a;
}
__device__ __forceinline__ void cpasync16(unsigned dst, const void* src) {
    asm volatile("cp.async.cg.shared.global [%0], [%1], 16;" :: "r"(dst), "l"(src) : "memory");
}
__device__ __forceinline__ void cp_commit() {
    asm volatile("cp.async.commit_group;" ::: "memory");
}
template <int N> __device__ __forceinline__ void cp_wait() {
    asm volatile("cp.async.wait_group %0;" :: "n"(N) : "memory");
}
__device__ __forceinline__ void ldmat_x4(unsigned (&r)[4], unsigned addr) {
    asm volatile("ldmatrix.sync.aligned.m8n8.x4.shared.b16 {%0,%1,%2,%3}, [%4];"
                 : "=r"(r[0]), "=r"(r[1]), "=r"(r[2]), "=r"(r[3]) : "r"(addr));
}
__device__ __forceinline__ void mma16816(float (&c)[4], const unsigned* a, const unsigned* b) {
    asm volatile("mma.sync.aligned.m16n8k16.row.col.f32.bf16.bf16.f32 "
                 "{%0,%1,%2,%3}, {%4,%5,%6,%7}, {%8,%9}, {%0,%1,%2,%3};"
                 : "+f"(c[0]), "+f"(c[1]), "+f"(c[2]), "+f"(c[3])
                 : "r"(a[0]), "r"(a[1]), "r"(a[2]), "r"(a[3]), "r"(b[0]), "r"(b[1]));
}
__device__ __forceinline__ unsigned swz128(unsigned off) { return off ^ ((off >> 3) & 0x70); }
__device__ __forceinline__ unsigned pkbf2(float a, float b) {
    __nv_bfloat162 t = __floats2bfloat162_rn(a, b);
    return *(unsigned*)&t;
}
__device__ __forceinline__ float bflo(float v) {
    __nv_bfloat16 h = __float2bfloat16(v);
    return v - __bfloat162float(h);
}
__device__ __forceinline__ float sigm(float x) { return 1.f / (1.f + expf(-x)); }

constexpr int STAGE3M = 98304;              // 96KB (64x64 3M)
constexpr int GEMM3M_SMEM = 2 * STAGE3M;    // 192KB
constexpr int GEMM_SMEM = 3 * 65536;        // 192KB

struct MmaCtx {
    int warpM, warpN;
    int a_m, a_k, b_n, b_k;
};
__device__ __forceinline__ MmaCtx make_ctx(int tid) {
    MmaCtx cx;
    int wid = tid >> 5, lane = tid & 31;
    cx.warpM = (wid & 3) * 32; cx.warpN = (wid >> 2) * 64;
    int lmat = lane >> 3, lrow = lane & 7;
    cx.a_m = (lmat & 1) * 8 + lrow; cx.a_k = (lmat >> 1) * 8;
    cx.b_n = (lmat >> 1) * 8 + lrow; cx.b_k = (lmat & 1) * 8;
    return cx;
}
__device__ __forceinline__ void mma_compute(const MmaCtx& cx, unsigned stg, float acc[2][8][4]) {
    const unsigned sA0 = stg, sA1 = stg + 16384u;
    const unsigned sB0 = stg + 32768u, sB1 = stg + 49152u;
#pragma unroll
    for (int ks = 0; ks < 4; ks++) {
        unsigned ah[2][4], al[2][4];
#pragma unroll
        for (int mt = 0; mt < 2; mt++) {
            int mm = cx.warpM + mt * 16 + cx.a_m;
            unsigned off = swz128((unsigned)(mm * 128 + (ks * 16 + cx.a_k) * 2));
            ldmat_x4(ah[mt], sA0 + off);
            ldmat_x4(al[mt], sA1 + off);
        }
        unsigned bh[8][2], bl[8][2];
#pragma unroll
        for (int np = 0; np < 4; np++) {
            int n = cx.warpN + np * 16 + cx.b_n;
            unsigned off = swz128((unsigned)(n * 128 + (ks * 16 + cx.b_k) * 2));
            unsigned rh[4], rl[4];
            ldmat_x4(rh, sB0 + off);
            ldmat_x4(rl, sB1 + off);
            bh[2*np][0]=rh[0]; bh[2*np][1]=rh[1]; bh[2*np+1][0]=rh[2]; bh[2*np+1][1]=rh[3];
            bl[2*np][0]=rl[0]; bl[2*np][1]=rl[1]; bl[2*np+1][0]=rl[2]; bl[2*np+1][1]=rl[3];
        }
#pragma unroll
        for (int mt = 0; mt < 2; mt++)
#pragma unroll
            for (int nt = 0; nt < 8; nt++) {
                mma16816(acc[mt][nt], ah[mt], bh[nt]);
                mma16816(acc[mt][nt], ah[mt], bl[nt]);
                mma16816(acc[mt][nt], al[mt], bh[nt]);
            }
    }
}
__device__ __forceinline__ void mma_stage_load(
    int tid, unsigned stg, int k0,
    const __nv_bfloat16* aPh, const __nv_bfloat16* aPl, int aK,
    const __nv_bfloat16* bPh, const __nv_bfloat16* bPl, int bK) {
    const __nv_bfloat16* aa[2] = { aPh, aPl };
    const __nv_bfloat16* bb[2] = { bPh, bPl };
#pragma unroll
    for (int hl = 0; hl < 2; hl++) {
        unsigned hOff = hl ? 16384u : 0u;
#pragma unroll
        for (int it = 0; it < 4; it++) {
            int idx = it * 256 + tid;
            int r = idx >> 3, c = (idx & 7) * 8;
            unsigned so = swz128((unsigned)(r * 128 + c * 2));
            cpasync16(stg + hOff + so, aa[hl] + (size_t)r * aK + k0 + c);
            cpasync16(stg + 32768u + hOff + so, bb[hl] + (size_t)r * bK + k0 + c);
        }
    }
    cp_commit();
}
__device__ __forceinline__ void stage_load_B(
    int tid, unsigned stg, int k0,
    const __nv_bfloat16* bPh, const __nv_bfloat16* bPl, int bK) {
    const __nv_bfloat16* bb[2] = { bPh, bPl };
#pragma unroll
    for (int hl = 0; hl < 2; hl++) {
        unsigned hOff = hl ? 16384u : 0u;
#pragma unroll
        for (int it = 0; it < 4; it++) {
            int idx = it * 256 + tid;
            int r = idx >> 3, c = (idx & 7) * 8;
            unsigned so = swz128((unsigned)(r * 128 + c * 2));
            cpasync16(stg + 32768u + hOff + so, bb[hl] + (size_t)r * bK + k0 + c);
        }
    }
    cp_commit();
}

// ---------------------------------------------------------------------------
// reductions
// ---------------------------------------------------------------------------
__device__ __forceinline__ float blockSum128(float v) {
    __shared__ float sh[4];
    int lane = threadIdx.x & 31, w = threadIdx.x >> 5;
#pragma unroll
    for (int o = 16; o; o >>= 1) v += __shfl_xor_sync(0xffffffffu, v, o);
    if (lane == 0) sh[w] = v;
    __syncthreads();
    float r = sh[0] + sh[1] + sh[2] + sh[3];
    __syncthreads();
    return r;
}
__device__ __forceinline__ float blockSum256(float v, float* sh) {
    int lane = threadIdx.x & 31, w = threadIdx.x >> 5;
#pragma unroll
    for (int o = 16; o; o >>= 1) v += __shfl_xor_sync(0xffffffffu, v, o);
    if (lane == 0) sh[w] = v;
    __syncthreads();
    float r = 0.f;
#pragma unroll
    for (int i = 0; i < 8; i++) r += sh[i];
    __syncthreads();
    return r;
}

// ---------------------------------------------------------------------------
// generic 3M 64x64-complex block body (shared by Wl / T / V kernels)
// Computes acc[3][2][2][4] for A-planes (aBase + c*DD) and B-planes
// (bPlane base pointers). K = 512, BK = 64, double-buffered.
// ---------------------------------------------------------------------------
struct Tile3M {
    float acc[3][2][2][4];
};
__device__ __forceinline__ void run_3m(
    int tid, unsigned sbase,
    const __nv_bfloat16* aPh0, const __nv_bfloat16* aPl0,   // A base (+c*DD inside)
    const __nv_bfloat16* bPh0, const __nv_bfloat16* bPl0,   // B base (+c*DD inside)
    int row0, int col0,
    int warpM, int warpN, int a_m, int a_k, int b_n, int b_k,
    Tile3M& T)
{
    const __nv_bfloat16* aP[3][2];
    const __nv_bfloat16* bP[3][2];
#pragma unroll
    for (int c = 0; c < 3; c++) {
        aP[c][0] = aPh0 + (size_t)c * DD + (size_t)row0 * Dc;
        aP[c][1] = aPl0 + (size_t)c * DD + (size_t)row0 * Dc;
        bP[c][0] = bPh0 + (size_t)c * DD + (size_t)col0 * Dc;
        bP[c][1] = bPl0 + (size_t)c * DD + (size_t)col0 * Dc;
    }
#pragma unroll
    for (int p = 0; p < 3; p++)
#pragma unroll
        for (int mt = 0; mt < 2; mt++)
#pragma unroll
            for (int nt = 0; nt < 2; nt++)
#pragma unroll
                for (int q = 0; q < 4; q++) T.acc[p][mt][nt][q] = 0.f;

    auto stage_load = [&](int ch, unsigned stg) {
        const int k0 = ch << 6;
#pragma unroll
        for (int c = 0; c < 3; c++)
#pragma unroll
            for (int hl = 0; hl < 2; hl++) {
                unsigned tOff = (unsigned)((c * 2 + hl) * 8192);
#pragma unroll
                for (int it = 0; it < 2; it++) {
                    int idx = it * 256 + tid;
                    int r = idx >> 3, cc = (idx & 7) * 8;
                    unsigned so = swz128((unsigned)(r * 128 + cc * 2));
                    cpasync16(stg + tOff + so, aP[c][hl] + (size_t)r * Dc + k0 + cc);
                    cpasync16(stg + 49152u + tOff + so, bP[c][hl] + (size_t)r * Dc + k0 + cc);
                }
            }
        cp_commit();
    };
    auto compute = [&](unsigned stg) {
#pragma unroll
        for (int ks = 0; ks < 4; ks++) {
            unsigned afh[3][2][4], afl[3][2][4];
#pragma unroll
            for (int c = 0; c < 3; c++)
#pragma unroll
                for (int mt = 0; mt < 2; mt++) {
                    int mm = warpM + mt * 16 + a_m;
                    unsigned off = swz128((unsigned)(mm * 128 + (ks * 16 + a_k) * 2));
                    ldmat_x4(afh[c][mt], stg + (unsigned)((c * 2 + 0) * 8192) + off);
                    ldmat_x4(afl[c][mt], stg + (unsigned)((c * 2 + 1) * 8192) + off);
                }
            unsigned bfh[3][2][2], bfl[3][2][2];
#pragma unroll
            for (int c = 0; c < 3; c++) {
                int n = warpN + b_n;
                unsigned off = swz128((unsigned)(n * 128 + (ks * 16 + b_k) * 2));
                unsigned rh[4], rl[4];
                ldmat_x4(rh, stg + 49152u + (unsigned)((c * 2 + 0) * 8192) + off);
                ldmat_x4(rl, stg + 49152u + (unsigned)((c * 2 + 1) * 8192) + off);
                bfh[c][0][0] = rh[0]; bfh[c][0][1] = rh[1];
                bfh[c][1][0] = rh[2]; bfh[c][1][1] = rh[3];
                bfl[c][0][0] = rl[0]; bfl[c][0][1] = rl[1];
                bfl[c][1][0] = rl[2]; bfl[c][1][1] = rl[3];
            }
#pragma unroll
            for (int p = 0; p < 3; p++)
#pragma unroll
                for (int mt = 0; mt < 2; mt++)
#pragma unroll
                    for (int nt = 0; nt < 2; nt++) {
                        mma16816(T.acc[p][mt][nt], afh[p][mt], bfh[p][nt]);
                        mma16816(T.acc[p][mt][nt], afh[p][mt], bfl[p][nt]);
                        mma16816(T.acc[p][mt][nt], afl[p][mt], bfh[p][nt]);
                    }
        }
    };

    const unsigned stg0 = sbase, stg1 = sbase + (unsigned)STAGE3M;
    const int nchunk = 8;
    stage_load(0, stg0);
    for (int ch = 0; ch < nchunk; ch++) {
        unsigned cur = (ch & 1) ? stg1 : stg0;
        if (ch + 1 < nchunk) { stage_load(ch + 1, (ch & 1) ? stg0 : stg1); cp_wait<1>(); }
        else cp_wait<0>();
        __syncthreads();
        compute(cur);
        __syncthreads();
    }
}

// ---------------------------------------------------------------------------
// Wl fused 3M GEMM. grid (8, 8, Mc). Z fp32 packed out.
// ---------------------------------------------------------------------------
__global__ void __launch_bounds__(256, 1) gemm_3m_wl(
    const __nv_bfloat16* __restrict__ Ah, const __nv_bfloat16* __restrict__ Al,
    const __nv_bfloat16* __restrict__ Wh, const __nv_bfloat16* __restrict__ Wl,
    float* __restrict__ outZ)
{
    extern __shared__ char smem_raw[];
    const unsigned sbase = smem_u32(smem_raw);
    const int tid = threadIdx.x;
    const int wid = tid >> 5, lane = tid & 31;
    const int m = blockIdx.z;
    const int col0 = blockIdx.x * 64;
    const int row0 = blockIdx.y * 64;
    const int warpM = (wid & 1) * 32, warpN = (wid >> 1) * 16;
    const int lmat = lane >> 3, lrow = lane & 7;
    const int a_m = (lmat & 1) * 8 + lrow, a_k = (lmat >> 1) * 8;
    const int b_n = (lmat >> 1) * 8 + lrow, b_k = (lmat & 1) * 8;

    Tile3M T;
    run_3m(tid, sbase, Ah, Al, Wh + (size_t)m * 3 * DD, Wl + (size_t)m * 3 * DD,
           row0, col0, warpM, warpN, a_m, a_k, b_n, b_k, T);

    const int erow = lane >> 2, ecol = (lane & 3) * 2;
#pragma unroll
    for (int mt = 0; mt < 2; mt++)
#pragma unroll
        for (int nt = 0; nt < 2; nt++)
#pragma unroll
            for (int half = 0; half < 2; half++) {
                int rowG = row0 + warpM + mt * 16 + erow + half * 8;
                int colG = col0 + warpN + nt * 8 + ecol;
                float m1a = T.acc[0][mt][nt][half * 2],     m1b = T.acc[0][mt][nt][half * 2 + 1];
                float m2a = T.acc[1][mt][nt][half * 2],     m2b = T.acc[1][mt][nt][half * 2 + 1];
                float m3a = T.acc[2][mt][nt][half * 2],     m3b = T.acc[2][mt][nt][half * 2 + 1];
                float* o = outZ + ((size_t)m * ROWS + rowG) * E2 + colG;
                o[0] = m1a - m2a; o[1] = m1b - m2b;
                o[Dc] = m3a - m1a - m2a; o[Dc + 1] = m3b - m1b - m2b;
            }
}

// ---------------------------------------------------------------------------
// FUSED T + V kernel. grid (512), uniform 64x64-complex 3M blocks:
//   bid < 256 -> T = z*H   (B planes 12 + m*3 + c, packed row-major out)
//   else      -> V = z*Wv  (B planes 36 + m*3 + c, transposed out)
// ---------------------------------------------------------------------------
__global__ void __launch_bounds__(256, 1) gemm_TV(
    const __nv_bfloat16* __restrict__ Zh_, const __nv_bfloat16* __restrict__ Zl_,
    const __nv_bfloat16* __restrict__ WH, const __nv_bfloat16* __restrict__ WL,
    __nv_bfloat16* __restrict__ Th_, __nv_bfloat16* __restrict__ Tl_)
{
    extern __shared__ char smem_raw[];
    const unsigned sbase = smem_u32(smem_raw);
    const int tid = threadIdx.x;
    const int bid = blockIdx.x;
    const int wid = tid >> 5, lane = tid & 31;
    const int isV = bid >= 256;
    const int tb = bid & 255;
    const int m = tb >> 6;
    const int row0 = ((tb >> 3) & 7) * 64;
    const int col0 = (tb & 7) * 64;
    const int warpM = (wid & 1) * 32, warpN = (wid >> 1) * 16;
    const int lmat = lane >> 3, lrow = lane & 7;
    const int a_m = (lmat & 1) * 8 + lrow, a_k = (lmat >> 1) * 8;
    const int b_n = (lmat >> 1) * 8 + lrow, b_k = (lmat & 1) * 8;

    const size_t bPlane = (size_t)((isV ? 36 : 12) + m * 3) * DD;
    Tile3M T;
    run_3m(tid, sbase,
           Zh_ + (size_t)m * 3 * DD, Zl_ + (size_t)m * 3 * DD,
           WH + bPlane, WL + bPlane,
           row0, col0, warpM, warpN, a_m, a_k, b_n, b_k, T);

    const int erow = lane >> 2, ecol = (lane & 3) * 2;
#pragma unroll
    for (int mt = 0; mt < 2; mt++)
#pragma unroll
        for (int nt = 0; nt < 2; nt++)
#pragma unroll
            for (int half = 0; half < 2; half++) {
                int rowG = row0 + warpM + mt * 16 + erow + half * 8;
                int colG = col0 + warpN + nt * 8 + ecol;   // complex col
                float m1a = T.acc[0][mt][nt][half * 2],     m1b = T.acc[0][mt][nt][half * 2 + 1];
                float m2a = T.acc[1][mt][nt][half * 2],     m2b = T.acc[1][mt][nt][half * 2 + 1];
                float m3a = T.acc[2][mt][nt][half * 2],     m3b = T.acc[2][mt][nt][half * 2 + 1];
                float yr0 = m1a - m2a,       yr1 = m1b - m2b;
                float yi0 = m3a - m1a - m2a, yi1 = m3b - m1b - m2b;
                if (!isV) {
                    size_t base = (size_t)m * (ROWS * E2) + (size_t)rowG * E2 + colG;
                    *(unsigned*)(Th_ + base) = pkbf2(yr0, yr1);
                    *(unsigned*)(Tl_ + base) = pkbf2(bflo(yr0), bflo(yr1));
                    *(unsigned*)(Th_ + base + Dc) = pkbf2(yi0, yi1);
                    *(unsigned*)(Tl_ + base + Dc) = pkbf2(bflo(yi0), bflo(yi1));
                } else {
                    const int b = rowG >> 7, s = rowG & 127;
                    size_t o = ((size_t)(m * 4 + b) * E2 + colG) * Sc + s;
                    g_Vth[o] = __float2bfloat16(yr0);
                    g_Vtl[o] = __float2bfloat16(bflo(yr0));
                    g_Vth[o + Sc] = __float2bfloat16(yr1);
                    g_Vtl[o + Sc] = __float2bfloat16(bflo(yr1));
                    size_t oi = o + (size_t)Dc * Sc;
                    g_Vth[oi] = __float2bfloat16(yi0);
                    g_Vtl[oi] = __float2bfloat16(bflo(yi0));
                    g_Vth[oi + Sc] = __float2bfloat16(yi1);
                    g_Vtl[oi + Sc] = __float2bfloat16(bflo(yi1));
                }
            }
}

// ---------------------------------------------------------------------------
// QK logits GEMM: split-K atomic, B from Z planes (K-concat). grid (1,8,16).
// ---------------------------------------------------------------------------
__global__ void __launch_bounds__(256, 1) gemm_qk(
    const __nv_bfloat16* __restrict__ Ah, const __nv_bfloat16* __restrict__ Al,
    const __nv_bfloat16* __restrict__ Bh, const __nv_bfloat16* __restrict__ Bl,
    float* __restrict__ outF)
{
    extern __shared__ char smem_raw[];
    const unsigned sbase = smem_u32(smem_raw);
    const int tid = threadIdx.x, lane = tid & 31;
    const int z = blockIdx.z;
    const int kbase = blockIdx.y * 128;
    MmaCtx cx = make_ctx(tid);

    const __nv_bfloat16* aPh = Ah + (size_t)z * (Sc * E2) + kbase;
    const __nv_bfloat16* aPl = Al + (size_t)z * (Sc * E2) + kbase;
    const int m_ = z >> 2, b_ = z & 3;
    const int pl = kbase >> 9;
    const size_t boff = (size_t)(m_ * 3 + pl) * DD + (size_t)(b_ * 128) * 512 + (kbase & 511);
    const __nv_bfloat16* bPh = Bh + boff;
    const __nv_bfloat16* bPl = Bl + boff;

    float acc[2][8][4];
#pragma unroll
    for (int mt = 0; mt < 2; mt++)
#pragma unroll
        for (int nt = 0; nt < 8; nt++)
#pragma unroll
            for (int q = 0; q < 4; q++) acc[mt][nt][q] = 0.f;

    auto stg = [&](int i) { return sbase + (unsigned)((i % 3) * 65536); };
    mma_stage_load(tid, stg(0), 0, aPh, aPl, E2, bPh, bPl, 512);
    mma_stage_load(tid, stg(1), 64, aPh, aPl, E2, bPh, bPl, 512);
    cp_wait<1>();
    __syncthreads();
    mma_compute(cx, stg(0), acc);
    __syncthreads();
    cp_wait<0>();
    __syncthreads();
    mma_compute(cx, stg(1), acc);

    const int erow = lane >> 2, ecol = (lane & 3) * 2;
#pragma unroll
    for (int mt = 0; mt < 2; mt++)
#pragma unroll
        for (int nt = 0; nt < 8; nt++) {
            const float* c = acc[mt][nt];
#pragma unroll
            for (int half = 0; half < 2; half++) {
                int rowG = cx.warpM + mt * 16 + erow + half * 8;
                int colG = cx.warpN + nt * 8 + ecol;
                float* o = outF + (size_t)z * (Sc * Sc) + (size_t)rowG * Sc + colG;
                atomicAdd(o + 0, c[half * 2 + 0]);
                atomicAdd(o + 1, c[half * 2 + 1]);
            }
        }
}

// ---------------------------------------------------------------------------
// AV GEMM with FUSED softmax. grid (8, 1, 16).
// ---------------------------------------------------------------------------
__global__ void __launch_bounds__(256, 1) gemm_avsm(
    const __nv_bfloat16* __restrict__ Vth_, const __nv_bfloat16* __restrict__ Vtl_,
    float* __restrict__ P_,
    const float* __restrict__ score_w, const float* __restrict__ conf_w,
    const float* __restrict__ halt_w)
{
    extern __shared__ char smem_raw[];
    const unsigned sbase = smem_u32(smem_raw);
    float* slog = (float*)(smem_raw + 131072);
    const int tid = threadIdx.x;
    const int wid = tid >> 5, lane = tid & 31;
    const int z = blockIdx.z;
    const int col0 = blockIdx.x * 128;
    MmaCtx cx = make_ctx(tid);

    const __nv_bfloat16* bH = Vth_ + (size_t)z * (E2 * Sc) + (size_t)col0 * Sc;
    const __nv_bfloat16* bL = Vtl_ + (size_t)z * (E2 * Sc) + (size_t)col0 * Sc;
    stage_load_B(tid, sbase, 0, bH, bL, Sc);
    stage_load_B(tid, sbase + 65536u, 64, bH, bL, Sc);

    const float4* lg4 = (const float4*)(g_logits + (size_t)z * (Sc * Sc));
    float4* slog4 = (float4*)slog;
#pragma unroll
    for (int i = 0; i < 16; i++) slog4[i * 256 + tid] = lg4[i * 256 + tid];
    __syncthreads();

#pragma unroll
    for (int i = 0; i < 16; i++) {
        int row = (wid << 4) + i;
        float4 v4 = *(const float4*)(slog + row * 128 + lane * 4);
        float v0 = v4.x * SCALEF, v1 = v4.y * SCALEF, v2 = v4.z * SCALEF, v3 = v4.w * SCALEF;
        float mx = fmaxf(fmaxf(v0, v1), fmaxf(v2, v3));
#pragma unroll
        for (int o = 16; o; o >>= 1) mx = fmaxf(mx, __shfl_xor_sync(0xffffffffu, mx, o));
        float e0 = expf(v0 - mx), e1 = expf(v1 - mx), e2 = expf(v2 - mx), e3 = expf(v3 - mx);
        float su = e0 + e1 + e2 + e3;
#pragma unroll
        for (int o = 16; o; o >>= 1) su += __shfl_xor_sync(0xffffffffu, su, o);
        float inv = 1.f / su;
        float a0 = e0 * inv, a1 = e1 * inv, a2 = e2 * inv, a3 = e3 * inv;
        unsigned chOff = (lane >> 4) ? 65536u : 0u;
        unsigned so = swz128((unsigned)(row * 128 + (lane & 15) * 8));
        *(unsigned*)(smem_raw + chOff + so)         = pkbf2(a0, a1);
        *(unsigned*)(smem_raw + chOff + so + 4)     = pkbf2(a2, a3);
        *(unsigned*)(smem_raw + chOff + 16384 + so)     = pkbf2(bflo(a0), bflo(a1));
        *(unsigned*)(smem_raw + chOff + 16384 + so + 4) = pkbf2(bflo(a2), bflo(a3));
    }

    float acc[2][8][4];
#pragma unroll
    for (int mt = 0; mt < 2; mt++)
#pragma unroll
        for (int nt = 0; nt < 8; nt++)
#pragma unroll
            for (int q = 0; q < 4; q++) acc[mt][nt][q] = 0.f;

    cp_wait<1>();
    __syncthreads();
    mma_compute(cx, sbase, acc);
    cp_wait<0>();
    __syncthreads();
    mma_compute(cx, sbase + 65536u, acc);

    const int erow = lane >> 2, ecol = (lane & 3) * 2;
    const int m = z >> 2;
    float dots[2][2][3];
#pragma unroll
    for (int mt = 0; mt < 2; mt++)
#pragma unroll
        for (int half = 0; half < 2; half++)
#pragma unroll
            for (int j = 0; j < 3; j++) dots[mt][half][j] = 0.f;
#pragma unroll
    for (int mt = 0; mt < 2; mt++)
#pragma unroll
        for (int nt = 0; nt < 8; nt++) {
            float* c = acc[mt][nt];
#pragma unroll
            for (int half = 0; half < 2; half++) {
                int rowG = cx.warpM + mt * 16 + erow + half * 8;
                int colG = col0 + cx.warpN + nt * 8 + ecol;
                float v0 = c[half * 2 + 0], v1 = c[half * 2 + 1];
                int d0 = colG & 511, d1 = (colG + 1) & 511;
                v0 *= g_gate[m * Dc + d0];
                v1 *= g_gate[m * Dc + d1];
                dots[mt][half][0] += v0 * score_w[m * E2 + colG] + v1 * score_w[m * E2 + colG + 1];
                dots[mt][half][1] += v0 * conf_w[m * E2 + colG]  + v1 * conf_w[m * E2 + colG + 1];
                dots[mt][half][2] += v0 * halt_w[m * E2 + colG]  + v1 * halt_w[m * E2 + colG + 1];
                float* o = P_ + (size_t)z * (Sc * E2) + (size_t)rowG * E2 + colG;
                o[0] = v0; o[1] = v1;
            }
        }
#pragma unroll
    for (int mt = 0; mt < 2; mt++)
#pragma unroll
        for (int half = 0; half < 2; half++) {
#pragma unroll
            for (int j = 0; j < 3; j++) {
                dots[mt][half][j] += __shfl_xor_sync(0xffffffffu, dots[mt][half][j], 1);
                dots[mt][half][j] += __shfl_xor_sync(0xffffffffu, dots[mt][half][j], 2);
            }
            if ((lane & 3) == 0) {
                int rowG = cx.warpM + mt * 16 + erow + half * 8;
                int srow = z * Sc + rowG;
                atomicAdd(&g_score[srow], dots[mt][half][0]);
                atomicAdd(&g_conf[srow],  dots[mt][half][1]);
                atomicAdd(&g_halt[srow],  dots[mt][half][2]);
            }
        }
}

// ---------------------------------------------------------------------------
// one-time H^T GEMM: z = m*3+comp; C[d'][d] = sum_e Ak[m][d'][e]*Aq_c[m][d][e]
// writes split-bf16 into WP plane 12+z. grid (4,4,12).
// ---------------------------------------------------------------------------
__global__ void __launch_bounds__(256, 1) gemm_H(
    const __nv_bfloat16* __restrict__ ABh_, const __nv_bfloat16* __restrict__ ABl_,
    __nv_bfloat16* __restrict__ WPh_, __nv_bfloat16* __restrict__ WPl_)
{
    extern __shared__ char smem_raw[];
    const unsigned sbase = smem_u32(smem_raw);
    const int tid = threadIdx.x, lane = tid & 31;
    const int z = blockIdx.z;
    const int m = z / 3, comp = z % 3;
    const int col0 = blockIdx.x * 128, row0 = blockIdx.y * 128;
    MmaCtx cx = make_ctx(tid);

    const size_t akBase = (size_t)m * (512 * 1024);
    const size_t aqBase = (size_t)(1 + comp) * 2 * MM + (size_t)m * (512 * 1024);
    const __nv_bfloat16* aPh = ABh_ + akBase + (size_t)row0 * 1024;
    const __nv_bfloat16* aPl = ABl_ + akBase + (size_t)row0 * 1024;
    const __nv_bfloat16* bPh = ABh_ + aqBase + (size_t)col0 * 1024;
    const __nv_bfloat16* bPl = ABl_ + aqBase + (size_t)col0 * 1024;

    float acc[2][8][4];
#pragma unroll
    for (int mt = 0; mt < 2; mt++)
#pragma unroll
        for (int nt = 0; nt < 8; nt++)
#pragma unroll
            for (int q = 0; q < 4; q++) acc[mt][nt][q] = 0.f;

    const int nchunk = 16;
    auto stg = [&](int i) { return sbase + (unsigned)((i % 3) * 65536); };
    mma_stage_load(tid, stg(0), 0, aPh, aPl, 1024, bPh, bPl, 1024);
    mma_stage_load(tid, stg(1), 64, aPh, aPl, 1024, bPh, bPl, 1024);
    for (int ch = 0; ch < nchunk; ch++) {
        if (ch + 2 < nchunk) {
            mma_stage_load(tid, stg(ch + 2), (ch + 2) << 6, aPh, aPl, 1024, bPh, bPl, 1024);
            cp_wait<2>();
        } else if (ch + 1 < nchunk) cp_wait<1>();
        else cp_wait<0>();
        __syncthreads();
        mma_compute(cx, stg(ch), acc);
        __syncthreads();
    }

    const int erow = lane >> 2, ecol = (lane & 3) * 2;
#pragma unroll
    for (int mt = 0; mt < 2; mt++)
#pragma unroll
        for (int nt = 0; nt < 8; nt++) {
            const float* c = acc[mt][nt];
#pragma unroll
            for (int half = 0; half < 2; half++) {
                int rowG = row0 + cx.warpM + mt * 16 + erow + half * 8;
                int colG = col0 + cx.warpN + nt * 8 + ecol;
                float v0 = c[half * 2 + 0], v1 = c[half * 2 + 1];
                size_t base = (size_t)(12 + z) * DD + (size_t)rowG * 512 + colG;
                *(unsigned*)(WPh_ + base) = pkbf2(v0, v1);
                *(unsigned*)(WPl_ + base) = pkbf2(bflo(v0), bflo(v1));
            }
        }
}

// ---------------------------------------------------------------------------
// small kernels
// ---------------------------------------------------------------------------
__global__ void k_pack(const float* __restrict__ Wl_r, const float* __restrict__ Wl_i,
                       const float* __restrict__ Wv_r, const float* __restrict__ Wv_i) {
    size_t idx = (size_t)blockIdx.x * 256 + threadIdx.x;   // 24 * 2^18
    int p24 = (int)(idx >> 18);
    int r = (int)(idx & (DD - 1));
    int ty2 = p24 / 12, rem = p24 % 12, m = rem / 3, comp = rem % 3;
    const float* Wr = ty2 ? Wv_r : Wl_r;
    const float* Wi = ty2 ? Wv_i : Wl_i;
    size_t base = (size_t)m * DD + r;
    float v = (comp == 0) ? Wr[base] : (comp == 1) ? Wi[base] : (Wr[base] + Wi[base]);
    size_t out = (size_t)((ty2 ? 36 : 0) + rem) * DD + r;
    g_WPH[out] = __float2bfloat16(v);
    g_WPL[out] = __float2bfloat16(bflo(v));
}

// Ak [m][d][e1024] = [WkR[o][d] | WkI[o][d]] ; Aq planes:
// p0=[WqR|WqI], p1=[WqI|-WqR], p2=[WqR+WqI | WqI-WqR]. g = idx>>21.
__global__ void k_packQK(const float* __restrict__ Wq_r, const float* __restrict__ Wq_i,
                         const float* __restrict__ Wk_r, const float* __restrict__ Wk_i) {
    size_t idx = (size_t)blockIdx.x * 256 + threadIdx.x;   // 8 * 2^20
    int g = (int)(idx >> 21);
    int m = (int)((idx >> 19) & 3);
    int d = (int)((idx >> 10) & 511);
    int e = (int)(idx & 1023);
    int o = e & 511;
    bool hi = e >= 512;
    size_t w = (size_t)m * DD + (size_t)o * Dc + d;
    float v;
    if (g == 0)      v = hi ?  Wk_i[w] : Wk_r[w];
    else if (g == 1) v = hi ?  Wq_i[w] : Wq_r[w];
    else if (g == 2) v = hi ? -Wq_r[w] : Wq_i[w];
    else             v = hi ? (Wq_i[w] - Wq_r[w]) : (Wq_r[w] + Wq_i[w]);
    g_ABh[idx] = __float2bfloat16(v);
    g_ABl[idx] = __float2bfloat16(bflo(v));
}

__global__ void k_init(const float* __restrict__ xr, const float* __restrict__ xi,
                       const float* __restrict__ gate_mask) {
    int i = blockIdx.x * 256 + threadIdx.x;
    if (i < ROWS * Dc) {
        g_sr[i] = xr[i]; g_si[i] = xi[i];
        float cr = xr[i], ci = xi[i], cs = cr + ci;
        g_Ch[i] = __float2bfloat16(cr);          g_Cl[i] = __float2bfloat16(bflo(cr));
        g_Ch[DD + i] = __float2bfloat16(ci);     g_Cl[DD + i] = __float2bfloat16(bflo(ci));
        g_Ch[2 * DD + i] = __float2bfloat16(cs); g_Cl[2 * DD + i] = __float2bfloat16(bflo(cs));
    }
    if (i < ROWS * E2) g_acc[i] = 0.f;
    if (i < 16 * Sc * Sc) g_logits[i] = 0.f;
    if (i < NMBS) { g_score[i] = 0.f; g_conf[i] = 0.f; g_halt[i] = 0.f; }
    if (i < Bc * Kc * E2) g_mem[i] = 0.f;
    if (i < Bc * Kc) g_ptrst[i] = (i % Kc == 0) ? 1.f : 0.f;
    if (i < Mc * Dc) g_gate[i] = sigm(gate_mask[i]);
    if (i < Bc) g_rem[i] = 1.f;
    if (i < Bc * E2) {
        int b = i >> 10, e = i & 1023;
        const float* base = (e < Dc) ? (xr + (size_t)b * Sc * Dc + e)
                                     : (xi + (size_t)b * Sc * Dc + (e - Dc));
        float s = 0.f;
#pragma unroll 4
        for (int ss = 0; ss < Sc; ss++) s += base[(size_t)ss * Dc];
        g_flat[i] = s * (1.f / Sc);
    }
}

__global__ void k_norm(const float* __restrict__ ln_scale,
                       const float* __restrict__ ln_shift,
                       const float* __restrict__ mod_bias) {
    const int row = blockIdx.x;
    const int m = row >> 9, bs = row & 511;
    const float* zp = g_Z + (size_t)row * E2;
    const int t = threadIdx.x;
    float4 r4 = *(const float4*)(zp + 4 * t);
    float4 i4 = *(const float4*)(zp + Dc + 4 * t);
    float vr[4] = {r4.x, r4.y, r4.z, r4.w};
    float vi[4] = {i4.x, i4.y, i4.z, i4.w};
    float mg[4];
    float s = 0.f, ss = 0.f;
#pragma unroll
    for (int q = 0; q < 4; q++) {
        mg[q] = sqrtf(vr[q] * vr[q] + vi[q] * vi[q]) + EPSF;
        s += mg[q]; ss += mg[q] * mg[q];
    }
    float sum = blockSum128(s);
    float sumsq = blockSum128(ss);
    float mean = sum * (1.f / Dc);
    float var = (sumsq - (float)Dc * mean * mean) * (1.f / (Dc - 1));
    float rstd = rsqrtf(var + EPSF);
    float4 lsc = *(const float4*)(ln_scale + m * Dc + 4 * t);
    float4 lsh = *(const float4*)(ln_shift + m * Dc + 4 * t);
    float4 mb  = *(const float4*)(mod_bias + m * Dc + 4 * t);
    float lscv[4] = {lsc.x, lsc.y, lsc.z, lsc.w};
    float lshv[4] = {lsh.x, lsh.y, lsh.z, lsh.w};
    float mbv[4]  = {mb.x, mb.y, mb.z, mb.w};
    float fr[4], fi[4], fs[4];
#pragma unroll
    for (int q = 0; q < 4; q++) {
        float nm = (mg[q] - mean) * rstd * lscv[q] + lshv[q];
        float hyp = mg[q] - EPSF;
        float c, sn;
        if (hyp > 0.f) { float ih = 1.f / hyp; c = vr[q] * ih; sn = vi[q] * ih; }
        else { c = 1.f; sn = 0.f; }
        float zr2 = nm * c, zi2 = nm * sn;
        float nrm = fabsf(nm) + EPSF;
        float sc = fmaxf(nrm + mbv[q], 0.f) / nrm;
        fr[q] = zr2 * sc; fi[q] = zi2 * sc; fs[q] = fr[q] + fi[q];
    }
    const size_t off = (size_t)bs * Dc + 4 * t;
    __nv_bfloat16* oh0 = g_Zh + (size_t)(m * 3 + 0) * DD + off;
    __nv_bfloat16* ol0 = g_Zl + (size_t)(m * 3 + 0) * DD + off;
    *(uint2*)oh0 = make_uint2(pkbf2(fr[0], fr[1]), pkbf2(fr[2], fr[3]));
    *(uint2*)ol0 = make_uint2(pkbf2(bflo(fr[0]), bflo(fr[1])), pkbf2(bflo(fr[2]), bflo(fr[3])));
    __nv_bfloat16* oh1 = g_Zh + (size_t)(m * 3 + 1) * DD + off;
    __nv_bfloat16* ol1 = g_Zl + (size_t)(m * 3 + 1) * DD + off;
    *(uint2*)oh1 = make_uint2(pkbf2(fi[0], fi[1]), pkbf2(fi[2], fi[3]));
    *(uint2*)ol1 = make_uint2(pkbf2(bflo(fi[0]), bflo(fi[1])), pkbf2(bflo(fi[2]), bflo(fi[3])));
    __nv_bfloat16* oh2 = g_Zh + (size_t)(m * 3 + 2) * DD + off;
    __nv_bfloat16* ol2 = g_Zl + (size_t)(m * 3 + 2) * DD + off;
    *(uint2*)oh2 = make_uint2(pkbf2(fs[0], fs[1]), pkbf2(fs[2], fs[3]));
    *(uint2*)ol2 = make_uint2(pkbf2(bflo(fs[0]), bflo(fs[1])), pkbf2(bflo(fs[2]), bflo(fs[3])));
}

__global__ void k_stack(const float* __restrict__ cw,  const float* __restrict__ cb,
                        const float* __restrict__ stw, const float* __restrict__ stb,
                        const float* __restrict__ scw, const float* __restrict__ scb,
                        const float* __restrict__ halt_b) {
    __shared__ float s_red[8];
    __shared__ float s_ptr[Kc], s_wmask[Kc];
    const int b = blockIdx.x, t = threadIdx.x;
    const int e0 = 4 * t;

    float4 fv = *(float4*)(g_flat + b * E2 + e0);
    *(float4*)(g_flat + b * E2 + e0) = make_float4(0.f, 0.f, 0.f, 0.f);

    float a0 = fv.x * cw[e0 * 3]     + fv.y * cw[(e0 + 1) * 3]     + fv.z * cw[(e0 + 2) * 3]     + fv.w * cw[(e0 + 3) * 3];
    float a1 = fv.x * cw[e0 * 3 + 1] + fv.y * cw[(e0 + 1) * 3 + 1] + fv.z * cw[(e0 + 2) * 3 + 1] + fv.w * cw[(e0 + 3) * 3 + 1];
    float a2 = fv.x * cw[e0 * 3 + 2] + fv.y * cw[(e0 + 1) * 3 + 2] + fv.z * cw[(e0 + 2) * 3 + 2] + fv.w * cw[(e0 + 3) * 3 + 2];
    a0 = blockSum256(a0, s_red); a1 = blockSum256(a1, s_red); a2 = blockSum256(a2, s_red);
    a0 += cb[0]; a1 += cb[1]; a2 += cb[2];
    float mx3 = fmaxf(a0, fmaxf(a1, a2));
    float e0e = expf(a0 - mx3), e1e = expf(a1 - mx3), e2e = expf(a2 - mx3);
    float is3 = 1.f / (e0e + e1e + e2e);
    float push = e0e * is3, pop = e1e * is3, noop = e2e * is3;

    if (t < Kc) {
        float* P = g_ptrst + b * Kc;
        float pu = P[(t + Kc - 1) % Kc];
        float pd = P[(t + 1) % Kc];
        float pc = P[t];
        float np = push * pu + pop * pd + noop * pc;
        float s = np;
#pragma unroll
        for (int o = 16; o; o >>= 1) s += __shfl_xor_sync(0xffffffffu, s, o);
        np /= (s + EPSF);
        P[t] = np;
        s_ptr[t] = np;
        s_wmask[t] = push * pu;
    }
    __syncthreads();

    float4 racc = make_float4(0.f, 0.f, 0.f, 0.f);
#pragma unroll
    for (int k = 0; k < Kc; k++) {
        float w = s_wmask[k], pk = s_ptr[k];
        float4* mp = (float4*)(g_mem + ((size_t)(b * Kc + k)) * E2 + e0);
        float4 old = *mp;
        float4 nm = make_float4(fmaf(w, fv.x - old.x, old.x), fmaf(w, fv.y - old.y, old.y),
                                fmaf(w, fv.z - old.z, old.z), fmaf(w, fv.w - old.w, old.w));
        *mp = nm;
        racc.x += nm.x * pk; racc.y += nm.y * pk; racc.z += nm.z * pk; racc.w += nm.w * pk;
    }
    *(float4*)(g_read + b * E2 + e0) = racc;
    float4 w1 = *(const float4*)(stw + e0);
    float4 w2 = *(const float4*)(scw + e0);
    float s1 = racc.x * w1.x + racc.y * w1.y + racc.z * w1.z + racc.w * w1.w;
    float s2 = racc.x * w2.x + racc.y * w2.y + racc.z * w2.z + racc.w * w2.w;
    float h = 0.f;
    for (int idx = t; idx < Mc * Sc; idx += 256) {
        int mIdx = idx >> 7;
        h += sigm(g_halt[mIdx * NBS + b * Sc + (idx & 127)] + halt_b[mIdx]);
    }
    s1 = blockSum256(s1, s_red); s2 = blockSum256(s2, s_red); h = blockSum256(h, s_red);
    if (t == 0) {
        g_stsc[b] = s1 + stb[0];
        g_stcf[b] = sigm(s2 + scb[0]);
        float p = h * (1.f / (Mc * Sc));
        float rm = g_rem[b];
        g_coef[b] = p * rm;
        g_rem[b] = rm * (1.f - p);
    }
}

// combine + state/acc + NEXT-step C + flat accum + logits & dot-buffer zero
__global__ void k_combine(const float* __restrict__ xr, const float* __restrict__ xi,
                          const float* __restrict__ score_b, const float* __restrict__ conf_b) {
    const int bs = blockIdx.x;
    const int b = bs >> 7;
    float l[5];
#pragma unroll
    for (int m = 0; m < Mc; m++) {
        float sA = g_score[m * NBS + bs] + score_b[m];
        float cA = sigm(g_conf[m * NBS + bs] + conf_b[m]);
        l[m] = sA * cA;
    }
    l[4] = g_stsc[b] * g_stcf[b];
    __syncthreads();
    if (threadIdx.x == 0) {
#pragma unroll
        for (int m = 0; m < Mc; m++) {
            g_score[m * NBS + bs] = 0.f;
            g_conf[m * NBS + bs] = 0.f;
            g_halt[m * NBS + bs] = 0.f;
        }
    }
    float mx = l[0];
#pragma unroll
    for (int m = 1; m < 5; m++) mx = fmaxf(mx, l[m]);
    float w[5], s = 0.f;
#pragma unroll
    for (int m = 0; m < 5; m++) { w[m] = expf(l[m] - mx); s += w[m]; }
    float is = 1.f / s;
#pragma unroll
    for (int m = 0; m < 5; m++) w[m] *= is;
    float cf = g_coef[b];
    const int t = threadIdx.x;
    const int d0 = 4 * t;

    float4 rd = *(const float4*)(g_read + b * E2 + d0);
    float4 ri = *(const float4*)(g_read + b * E2 + Dc + d0);
    float nr[4] = {w[4] * rd.x, w[4] * rd.y, w[4] * rd.z, w[4] * rd.w};
    float ni[4] = {w[4] * ri.x, w[4] * ri.y, w[4] * ri.z, w[4] * ri.w};
#pragma unroll
    for (int m = 0; m < Mc; m++) {
        const float* pb = g_P + ((size_t)m * NBS + bs) * E2;
        float4 pr = *(const float4*)(pb + d0);
        float4 pi = *(const float4*)(pb + Dc + d0);
        nr[0] += w[m] * pr.x; nr[1] += w[m] * pr.y; nr[2] += w[m] * pr.z; nr[3] += w[m] * pr.w;
        ni[0] += w[m] * pi.x; ni[1] += w[m] * pi.y; ni[2] += w[m] * pi.z; ni[3] += w[m] * pi.w;
    }
    *(float4*)(g_sr + (size_t)bs * Dc + d0) = make_float4(nr[0], nr[1], nr[2], nr[3]);
    *(float4*)(g_si + (size_t)bs * Dc + d0) = make_float4(ni[0], ni[1], ni[2], ni[3]);
    float4 a0 = *(float4*)(g_acc + (size_t)bs * E2 + d0);
    float4 a1 = *(float4*)(g_acc + (size_t)bs * E2 + Dc + d0);
    a0.x += cf * nr[0]; a0.y += cf * nr[1]; a0.z += cf * nr[2]; a0.w += cf * nr[3];
    a1.x += cf * ni[0]; a1.y += cf * ni[1]; a1.z += cf * ni[2]; a1.w += cf * ni[3];
    *(float4*)(g_acc + (size_t)bs * E2 + d0) = a0;
    *(float4*)(g_acc + (size_t)bs * E2 + Dc + d0) = a1;

    float4 x0 = *(const float4*)(xr + (size_t)bs * Dc + d0);
    float4 x1 = *(const float4*)(xi + (size_t)bs * Dc + d0);
    float cr[4] = {0.5f * (x0.x + nr[0]), 0.5f * (x0.y + nr[1]), 0.5f * (x0.z + nr[2]), 0.5f * (x0.w + nr[3])};
    float ci[4] = {0.5f * (x1.x + ni[0]), 0.5f * (x1.y + ni[1]), 0.5f * (x1.z + ni[2]), 0.5f * (x1.w + ni[3])};
    float cs[4] = {cr[0] + ci[0], cr[1] + ci[1], cr[2] + ci[2], cr[3] + ci[3]};
    const size_t co = (size_t)bs * Dc + d0;
    *(uint2*)(g_Ch + co) = make_uint2(pkbf2(cr[0], cr[1]), pkbf2(cr[2], cr[3]));
    *(uint2*)(g_Cl + co) = make_uint2(pkbf2(bflo(cr[0]), bflo(cr[1])), pkbf2(bflo(cr[2]), bflo(cr[3])));
    *(uint2*)(g_Ch + DD + co) = make_uint2(pkbf2(ci[0], ci[1]), pkbf2(ci[2], ci[3]));
    *(uint2*)(g_Cl + DD + co) = make_uint2(pkbf2(bflo(ci[0]), bflo(ci[1])), pkbf2(bflo(ci[2]), bflo(ci[3])));
    *(uint2*)(g_Ch + 2 * DD + co) = make_uint2(pkbf2(cs[0], cs[1]), pkbf2(cs[2], cs[3]));
    *(uint2*)(g_Cl + 2 * DD + co) = make_uint2(pkbf2(bflo(cs[0]), bflo(cs[1])), pkbf2(bflo(cs[2]), bflo(cs[3])));

    constexpr float invS = 1.f / Sc;
#pragma unroll
    for (int q = 0; q < 4; q++) {
        atomicAdd(g_flat + b * E2 + d0 + q, nr[q] * invS);
        atomicAdd(g_flat + b * E2 + Dc + d0 + q, ni[q] * invS);
    }
    *(float4*)(g_logits + (size_t)bs * 512 + d0) = make_float4(0.f, 0.f, 0.f, 0.f);
}

__global__ void k_final(float* __restrict__ out) {
    int i = blockIdx.x * 256 + threadIdx.x;
    int bs = i >> 10, e = i & 1023;
    int b = bs >> 7;
    float st = (e < Dc) ? g_sr[(size_t)bs * Dc + e]
                        : g_si[(size_t)bs * Dc + (e - Dc)];
    out[i] = g_acc[i] + g_rem[b] * st;
}

// ---------------------------------------------------------------------------
extern "C" void kernel_launch(void* const* d_in, const int* in_sizes, int n_in,
                              void* d_out, int out_size) {
    const float* xr        = (const float*)d_in[0];
    const float* xi        = (const float*)d_in[1];
    const float* Wl_r      = (const float*)d_in[2];
    const float* Wl_i      = (const float*)d_in[3];
    const float* Wq_r      = (const float*)d_in[4];
    const float* Wq_i      = (const float*)d_in[5];
    const float* Wk_r      = (const float*)d_in[6];
    const float* Wk_i      = (const float*)d_in[7];
    const float* Wv_r      = (const float*)d_in[8];
    const float* Wv_i      = (const float*)d_in[9];
    const float* ln_scale  = (const float*)d_in[10];
    const float* ln_shift  = (const float*)d_in[11];
    const float* mod_bias  = (const float*)d_in[12];
    const float* gate_mask = (const float*)d_in[13];
    const float* score_w   = (const float*)d_in[14];
    const float* score_b   = (const float*)d_in[15];
    const float* conf_w    = (const float*)d_in[16];
    const float* conf_b    = (const float*)d_in[17];
    const float* halt_w    = (const float*)d_in[18];
    const float* halt_b    = (const float*)d_in[19];
    const float* ctrl_w    = (const float*)d_in[20];
    const float* ctrl_b    = (const float*)d_in[21];
    const float* st_score_w= (const float*)d_in[22];
    const float* st_score_b= (const float*)d_in[23];
    const float* st_conf_w = (const float*)d_in[24];
    const float* st_conf_b = (const float*)d_in[25];

    cudaFuncSetAttribute(gemm_3m_wl, cudaFuncAttributeMaxDynamicSharedMemorySize, GEMM3M_SMEM);
    cudaFuncSetAttribute(gemm_TV,    cudaFuncAttributeMaxDynamicSharedMemorySize, GEMM3M_SMEM);
    cudaFuncSetAttribute(gemm_qk,    cudaFuncAttributeMaxDynamicSharedMemorySize, GEMM_SMEM);
    cudaFuncSetAttribute(gemm_avsm,  cudaFuncAttributeMaxDynamicSharedMemorySize, GEMM_SMEM);
    cudaFuncSetAttribute(gemm_H,     cudaFuncAttributeMaxDynamicSharedMemorySize, GEMM_SMEM);

    __nv_bfloat16 *WPH, *WPL, *ABh, *ABl, *Ch, *Cl, *Zh, *Zl, *Th, *Tl, *Vth, *Vtl;
    float *Z, *LG, *P;
    cudaGetSymbolAddress((void**)&WPH, g_WPH);
    cudaGetSymbolAddress((void**)&WPL, g_WPL);
    cudaGetSymbolAddress((void**)&ABh, g_ABh);
    cudaGetSymbolAddress((void**)&ABl, g_ABl);
    cudaGetSymbolAddress((void**)&Ch, g_Ch);
    cudaGetSymbolAddress((void**)&Cl, g_Cl);
    cudaGetSymbolAddress((void**)&Z,  g_Z);
    cudaGetSymbolAddress((void**)&Zh, g_Zh);
    cudaGetSymbolAddress((void**)&Zl, g_Zl);
    cudaGetSymbolAddress((void**)&Th, g_Th);
    cudaGetSymbolAddress((void**)&Tl, g_Tl);
    cudaGetSymbolAddress((void**)&Vth, g_Vth);
    cudaGetSymbolAddress((void**)&Vtl, g_Vtl);
    cudaGetSymbolAddress((void**)&LG, g_logits);
    cudaGetSymbolAddress((void**)&P, g_P);

    // one-time setup
    k_pack<<<24 * (DD / 256), 256>>>(Wl_r, Wl_i, Wv_r, Wv_i);
    k_packQK<<<32768, 256>>>(Wq_r, Wq_i, Wk_r, Wk_i);
    gemm_H<<<dim3(4, 4, 12), 256, GEMM_SMEM>>>(ABh, ABl, WPH, WPL);
    k_init<<<2048, 256>>>(xr, xi, gate_mask);

    for (int step = 0; step < NSTEPS; step++) {
        gemm_3m_wl<<<dim3(8, 8, Mc), 256, GEMM3M_SMEM>>>(Ch, Cl, WPH, WPL, Z);
        k_norm<<<NMBS, 128>>>(ln_scale, ln_shift, mod_bias);
        // fused T (Karatsuba) + V: 512 uniform 3M blocks
        gemm_TV<<<512, 256, GEMM3M_SMEM>>>(Zh, Zl, WPH, WPL, Th, Tl);
        // logits = T . zf^T (split-K=8)
        gemm_qk<<<dim3(1, 8, 16), 256, GEMM_SMEM>>>(Th, Tl, Zh, Zl, LG);
        // AV with fused softmax + gate + dots
        gemm_avsm<<<dim3(8, 1, 16), 256, GEMM_SMEM>>>(Vth, Vtl, P, score_w, conf_w, halt_w);
        k_stack<<<Bc, 256>>>(ctrl_w, ctrl_b, st_score_w, st_score_b, st_conf_w, st_conf_b, halt_b);
        k_combine<<<NBS, 128>>>(xr, xi, score_b, conf_b);
    }
    k_final<<<2048, 256>>>((float*)d_out);
}